// round 1
// baseline (speedup 1.0000x reference)
#include <cuda_runtime.h>

// Problem constants (from reference): N=50000, E=300000, G=256, H=256, LAT=64
#define HF 256
#define GFG 256
#define LATF 64
#define NMAX 50000
#define BN_EPS 1e-5f

// ---- static scratch (no allocations allowed) ----
__device__ float g_X[NMAX * HF];    // 51.2 MB ping
__device__ float g_Y[NMAX * HF];    // 51.2 MB pong
__device__ float g_HG[GFG * HF];    // pooled per-graph sums
__device__ float g_HGW[GFG * HF];   // HG @ W1_bottom + B1
__device__ float g_S[HF];           // BN sum
__device__ float g_SS[HF];          // BN sum of squares

// ---------------- helpers ----------------
__device__ __forceinline__ float sp(float x) {
    // stable softplus: max(x,0) + log1p(exp(-|x|))
    return fmaxf(x, 0.f) + log1pf(__expf(-fabsf(x)));
}

__device__ __forceinline__ void red_add_v4(float* p, float4 v) {
    asm volatile("red.global.add.v4.f32 [%0], {%1,%2,%3,%4};"
                 :: "l"(p), "f"(v.x), "f"(v.y), "f"(v.z), "f"(v.w) : "memory");
}

__device__ __forceinline__ int lb(const int* __restrict__ a, int n, int key) {
    int lo = 0, hi = n;
    while (lo < hi) { int mid = (lo + hi) >> 1; if (a[mid] < key) lo = mid + 1; else hi = mid; }
    return lo;
}

// ---------------- kernels ----------------

// X = node_emb[node_type], Y = X (self-term init for conv1)
__global__ void k_embed(const int* __restrict__ nt, const float* __restrict__ emb, int n) {
    int i = blockIdx.x * blockDim.x + threadIdx.x;
    int total = n * (HF / 4);
    if (i >= total) return;
    int node = i / (HF / 4);
    int f4   = i % (HF / 4);
    float4 v = __ldg((const float4*)emb + (size_t)nt[node] * (HF / 4) + f4);
    ((float4*)g_X)[i] = v;
    ((float4*)g_Y)[i] = v;
}

// Y[dst] += softplus(X[src] + edge_emb[edge_type])   (Y pre-initialized to X)
__global__ void k_conv(const int* __restrict__ src, const int* __restrict__ dst,
                       const int* __restrict__ et, const float* __restrict__ ew, int e_cnt) {
    int i = blockIdx.x * blockDim.x + threadIdx.x;
    int e = i >> 6;
    if (e >= e_cnt) return;
    int seg = (i & 63) << 2;
    int s = __ldg(src + e), d = __ldg(dst + e), t = __ldg(et + e);
    float4 x = *(const float4*)(g_X + (size_t)s * HF + seg);
    float4 w = __ldg((const float4*)(ew + (size_t)t * HF + seg));
    float4 m;
    m.x = sp(x.x + w.x);
    m.y = sp(x.y + w.y);
    m.z = sp(x.z + w.z);
    m.w = sp(x.w + w.w);
    red_add_v4(g_Y + (size_t)d * HF + seg, m);
}

__global__ void k_zero_stats() {
    g_S[threadIdx.x] = 0.f;
    g_SS[threadIdx.x] = 0.f;
}

// per-feature sum / sumsq of g_Y[0:n, 0:h]
__global__ void k_stats(int n, int h) {
    int f = threadIdx.x;
    float s = 0.f, ss = 0.f;
    for (int r = blockIdx.x; r < n; r += gridDim.x) {
        float v = g_Y[(size_t)r * h + f];
        s += v;
        ss = fmaf(v, v, ss);
    }
    atomicAdd(&g_S[f], s);
    atomicAdd(&g_SS[f], ss);
}

__device__ __forceinline__ float bn1(float y, float s, float ss, float g, float b,
                                     float inv_n, bool act) {
    float mu  = s * inv_n;
    float var = ss * inv_n - mu * mu;
    float v = g * (y - mu) * rsqrtf(var + BN_EPS) + b;
    return act ? sp(v) : v;
}

// X = (act?)BN(Y); optionally also Y = same (self-term init for next conv)
template <bool ACT, bool COPY>
__global__ void k_apply(const float* __restrict__ gam, const float* __restrict__ bet,
                        int n, int h) {
    int i = blockIdx.x * blockDim.x + threadIdx.x;
    int total = n * (h / 4);
    if (i >= total) return;
    int f4 = i % (h / 4);
    float4 y  = ((const float4*)g_Y)[i];
    float4 S4 = ((const float4*)g_S)[f4];
    float4 Q4 = ((const float4*)g_SS)[f4];
    float4 G4 = __ldg((const float4*)gam + f4);
    float4 B4 = __ldg((const float4*)bet + f4);
    float inv_n = 1.f / (float)n;
    float4 o;
    o.x = bn1(y.x, S4.x, Q4.x, G4.x, B4.x, inv_n, ACT);
    o.y = bn1(y.y, S4.y, Q4.y, G4.y, B4.y, inv_n, ACT);
    o.z = bn1(y.z, S4.z, Q4.z, G4.z, B4.z, inv_n, ACT);
    o.w = bn1(y.w, S4.w, Q4.w, G4.w, B4.w, inv_n, ACT);
    ((float4*)g_X)[i] = o;
    if (COPY) ((float4*)g_Y)[i] = o;
}

// HG[g] = sum over nodes of graph g (batch sorted -> binary search, no atomics)
__global__ void k_pool(const int* __restrict__ batch, int n) {
    int g = blockIdx.x;
    int f = threadIdx.x;
    __shared__ int slo, shi;
    if (f == 0) { slo = lb(batch, n, g); shi = lb(batch, n, g + 1); }
    __syncthreads();
    float s = 0.f;
    for (int r = slo; r < shi; r++) s += g_X[(size_t)r * HF + f];
    g_HG[g * HF + f] = s;
}

// HGW[g][f] = sum_k HG[g][k] * W1[(H+k)][f] + B1[f]
__global__ void k_hgw(const float* __restrict__ W1, const float* __restrict__ B1) {
    int g = blockIdx.x;
    int f = threadIdx.x;
    __shared__ float hg[HF];
    hg[f] = g_HG[g * HF + f];
    __syncthreads();
    float acc = __ldg(B1 + f);
#pragma unroll 8
    for (int k = 0; k < HF; k++)
        acc = fmaf(hg[k], __ldg(W1 + (size_t)(HF + k) * HF + f), acc);
    g_HGW[g * HF + f] = acc;
}

// C[M,Nc] = A[M,K] @ W[K,Nc] (+epilogue). 64x64x16 tile, 256 threads, 4x4 microtile.
// MODE 0: += HGW[batch[row]]   (bias folded into HGW)
// MODE 1: += bias[col]
// MODE 2: += bias[col], split-write: cols<64 -> C[row*64+col], else C[M*64 + row*64 + col-64]
template <int MODE>
__global__ void k_gemm(const float* __restrict__ A, const float* __restrict__ W,
                       float* __restrict__ C, const float* __restrict__ bias,
                       const int* __restrict__ batch, int M, int K, int Nc) {
    __shared__ float As[16][64];
    __shared__ float Bs[16][64];
    int tid = threadIdx.x;
    int tx = tid & 15, ty = tid >> 4;
    int m0 = blockIdx.y * 64, n0 = blockIdx.x * 64;

    float acc[4][4] = {};

    int a_m = tid >> 2;          // 0..63
    int a_k = (tid & 3) << 2;    // 0,4,8,12
    int b_k = tid >> 4;          // 0..15
    int b_n = (tid & 15) << 2;   // 0..60

    int arow = m0 + a_m;
    if (arow >= M) arow = M - 1;
    const float* Aptr = A + (size_t)arow * K + a_k;
    const float* Wptr = W + (size_t)b_k * Nc + n0 + b_n;

    for (int kt = 0; kt < K; kt += 16) {
        float4 av = *(const float4*)(Aptr + kt);
        float4 wv = __ldg((const float4*)(Wptr + (size_t)kt * Nc));
        As[a_k + 0][a_m] = av.x;
        As[a_k + 1][a_m] = av.y;
        As[a_k + 2][a_m] = av.z;
        As[a_k + 3][a_m] = av.w;
        *(float4*)&Bs[b_k][b_n] = wv;
        __syncthreads();
#pragma unroll
        for (int k = 0; k < 16; k++) {
            float4 a = *(float4*)&As[k][ty << 2];
            float4 b = *(float4*)&Bs[k][tx << 2];
            acc[0][0] = fmaf(a.x, b.x, acc[0][0]);
            acc[0][1] = fmaf(a.x, b.y, acc[0][1]);
            acc[0][2] = fmaf(a.x, b.z, acc[0][2]);
            acc[0][3] = fmaf(a.x, b.w, acc[0][3]);
            acc[1][0] = fmaf(a.y, b.x, acc[1][0]);
            acc[1][1] = fmaf(a.y, b.y, acc[1][1]);
            acc[1][2] = fmaf(a.y, b.z, acc[1][2]);
            acc[1][3] = fmaf(a.y, b.w, acc[1][3]);
            acc[2][0] = fmaf(a.z, b.x, acc[2][0]);
            acc[2][1] = fmaf(a.z, b.y, acc[2][1]);
            acc[2][2] = fmaf(a.z, b.z, acc[2][2]);
            acc[2][3] = fmaf(a.z, b.w, acc[2][3]);
            acc[3][0] = fmaf(a.w, b.x, acc[3][0]);
            acc[3][1] = fmaf(a.w, b.y, acc[3][1]);
            acc[3][2] = fmaf(a.w, b.z, acc[3][2]);
            acc[3][3] = fmaf(a.w, b.w, acc[3][3]);
        }
        __syncthreads();
    }

#pragma unroll
    for (int i = 0; i < 4; i++) {
        int row = m0 + (ty << 2) + i;
        if (row >= M) continue;
        int col = n0 + (tx << 2);
        float4 v = make_float4(acc[i][0], acc[i][1], acc[i][2], acc[i][3]);
        if (MODE == 0) {
            int bg = batch[row];
            float4 hw = *(const float4*)(g_HGW + (size_t)bg * HF + col);
            v.x += hw.x; v.y += hw.y; v.z += hw.z; v.w += hw.w;
            *(float4*)(C + (size_t)row * Nc + col) = v;
        } else {
            float4 b4 = __ldg((const float4*)(bias + col));
            v.x += b4.x; v.y += b4.y; v.z += b4.z; v.w += b4.w;
            if (MODE == 1) {
                *(float4*)(C + (size_t)row * Nc + col) = v;
            } else {
                if (col < LATF)
                    *(float4*)(C + (size_t)row * LATF + col) = v;
                else
                    *(float4*)(C + (size_t)M * LATF + (size_t)row * LATF + (col - LATF)) = v;
            }
        }
    }
}

// ---------------- launch ----------------
extern "C" void kernel_launch(void* const* d_in, const int* in_sizes, int n_in,
                              void* d_out, int out_size) {
    const int*   node_type = (const int*)d_in[0];
    const int*   edge_type = (const int*)d_in[1];
    const int*   edge_index = (const int*)d_in[2];
    const int*   batch     = (const int*)d_in[3];
    const float* node_emb  = (const float*)d_in[4];
    const float* edge_emb  = (const float*)d_in[5];
    const float* g1 = (const float*)d_in[6],  *b1 = (const float*)d_in[7];
    const float* g2 = (const float*)d_in[8],  *b2 = (const float*)d_in[9];
    const float* g3 = (const float*)d_in[10], *b3 = (const float*)d_in[11];
    const float* go1 = (const float*)d_in[12], *bo1 = (const float*)d_in[13];
    const float* go2 = (const float*)d_in[14], *bo2 = (const float*)d_in[15];
    const float* W1 = (const float*)d_in[16], *B1 = (const float*)d_in[17];
    const float* W2 = (const float*)d_in[18], *B2 = (const float*)d_in[19];
    const float* W3 = (const float*)d_in[20], *B3 = (const float*)d_in[21];

    int N = in_sizes[0];
    int E = in_sizes[1];
    const int* src = edge_index;
    const int* dst = edge_index + E;

    float *pX, *pY;
    cudaGetSymbolAddress((void**)&pX, g_X);
    cudaGetSymbolAddress((void**)&pY, g_Y);

    const int TB = 256;
    int n_f4   = N * (HF / 4);
    int emb_gr = (n_f4 + TB - 1) / TB;
    int cv_gr  = ((E << 6) + TB - 1) / TB;
    int ap_gr256 = emb_gr;
    int ap_gr128 = (N * (128 / 4) + TB - 1) / TB;
    int gy = (N + 63) / 64;

    // embed (X = emb, Y = X)
    k_embed<<<emb_gr, TB>>>(node_type, node_emb, N);

    // --- layer 1 ---
    k_conv<<<cv_gr, TB>>>(src, dst, edge_type, edge_emb, E);
    k_zero_stats<<<1, HF>>>();
    k_stats<<<512, HF>>>(N, HF);
    k_apply<true, true><<<ap_gr256, TB>>>(g1, b1, N, HF);

    // --- layer 2 ---
    k_conv<<<cv_gr, TB>>>(src, dst, edge_type, edge_emb, E);
    k_zero_stats<<<1, HF>>>();
    k_stats<<<512, HF>>>(N, HF);
    k_apply<true, true><<<ap_gr256, TB>>>(g2, b2, N, HF);

    // --- layer 3 (no act) ---
    k_conv<<<cv_gr, TB>>>(src, dst, edge_type, edge_emb, E);
    k_zero_stats<<<1, HF>>>();
    k_stats<<<512, HF>>>(N, HF);
    k_apply<false, false><<<ap_gr256, TB>>>(g3, b3, N, HF);

    // pooling + HGW = HG @ W1_bottom + B1
    k_pool<<<GFG, HF>>>(batch, N);
    k_hgw<<<GFG, HF>>>(W1, B1);

    // GEMM1: Y = X @ W1_top + HGW[batch]
    k_gemm<0><<<dim3(HF / 64, gy), TB>>>(pX, W1, pY, nullptr, batch, N, HF, HF);
    k_zero_stats<<<1, HF>>>();
    k_stats<<<512, HF>>>(N, HF);
    k_apply<true, false><<<ap_gr256, TB>>>(go1, bo1, N, HF);

    // GEMM2: Y = X @ W2 + B2   (Nc=128)
    k_gemm<1><<<dim3(128 / 64, gy), TB>>>(pX, W2, pY, B2, nullptr, N, HF, 128);
    k_zero_stats<<<1, HF>>>();
    k_stats<<<512, 128>>>(N, 128);
    k_apply<true, false><<<ap_gr128, TB>>>(go2, bo2, N, 128);

    // GEMM3: out = X @ W3 + B3, split into (mu, logvar)
    k_gemm<2><<<dim3(128 / 64, gy), TB>>>(pX, W3, (float*)d_out, B3, nullptr, N, 128, 128);

    (void)n_in; (void)out_size;
    (void)go1; (void)bo1; (void)go2; (void)bo2;
}

// round 3
// speedup vs baseline: 1.1599x; 1.1599x over previous
#include <cuda_runtime.h>
#include <cstdint>

// Problem constants: N=50000, E=300000, G=256, H=256, LAT=64
#define HF 256
#define GFG 256
#define LATF 64
#define NMAX 50000
#define BN_EPS 1e-5f

// ---- static scratch ----
__device__ __align__(128) float g_X[NMAX * HF];
__device__ __align__(128) float g_Y[NMAX * HF];
__device__ __align__(128) float g_HG[GFG * HF];
__device__ __align__(128) float g_HGW[GFG * HF];
__device__ float g_S[HF];
__device__ float g_SS[HF];

// ---------------- helpers ----------------
__device__ __forceinline__ float sp(float x) {
    return fmaxf(x, 0.f) + log1pf(__expf(-fabsf(x)));
}

__device__ __forceinline__ void red_add_v4(float* p, float4 v) {
    asm volatile("red.global.add.v4.f32 [%0], {%1,%2,%3,%4};"
                 :: "l"(p), "f"(v.x), "f"(v.y), "f"(v.z), "f"(v.w) : "memory");
}

__device__ __forceinline__ int lb(const int* __restrict__ a, int n, int key) {
    int lo = 0, hi = n;
    while (lo < hi) { int mid = (lo + hi) >> 1; if (a[mid] < key) lo = mid + 1; else hi = mid; }
    return lo;
}

__device__ __forceinline__ uint32_t f2tf32(float x) {
    uint32_t r;
    asm("cvt.rna.tf32.f32 %0, %1;" : "=r"(r) : "f"(x));
    return r;
}

__device__ __forceinline__ void mma_tf32(float c[4], uint32_t a0, uint32_t a1,
                                         uint32_t a2, uint32_t a3,
                                         uint32_t b0, uint32_t b1) {
    asm volatile(
        "mma.sync.aligned.m16n8k8.row.col.f32.tf32.tf32.f32 "
        "{%0,%1,%2,%3}, {%4,%5,%6,%7}, {%8,%9}, {%0,%1,%2,%3};"
        : "+f"(c[0]), "+f"(c[1]), "+f"(c[2]), "+f"(c[3])
        : "r"(a0), "r"(a1), "r"(a2), "r"(a3), "r"(b0), "r"(b1));
}

// ---------------- kernels ----------------

__global__ void k_embed(const int* __restrict__ nt, const float* __restrict__ emb, int n) {
    int i = blockIdx.x * blockDim.x + threadIdx.x;
    int total = n * (HF / 4);
    if (i >= total) return;
    int node = i / (HF / 4);
    int f4   = i % (HF / 4);
    float4 v = __ldg((const float4*)emb + (size_t)nt[node] * (HF / 4) + f4);
    ((float4*)g_X)[i] = v;
    ((float4*)g_Y)[i] = v;
}

// Y[dst] += softplus(X[src] + edge_emb[edge_type])
__global__ void k_conv(const int* __restrict__ src, const int* __restrict__ dst,
                       const int* __restrict__ et, const float* __restrict__ ew, int e_cnt) {
    int i = blockIdx.x * blockDim.x + threadIdx.x;
    int e = i >> 6;
    if (e >= e_cnt) return;
    int seg = (i & 63) << 2;
    int s = __ldg(src + e), d = __ldg(dst + e), t = __ldg(et + e);
    float4 x = *(const float4*)(g_X + (size_t)s * HF + seg);
    float4 w = __ldg((const float4*)(ew + (size_t)t * HF + seg));
    float4 m;
    m.x = sp(x.x + w.x);
    m.y = sp(x.y + w.y);
    m.z = sp(x.z + w.z);
    m.w = sp(x.w + w.w);
    red_add_v4(g_Y + (size_t)d * HF + seg, m);
}

__global__ void k_zero_stats() {
    g_S[threadIdx.x] = 0.f;
    g_SS[threadIdx.x] = 0.f;
}

// per-feature sum / sumsq of g_Y[0:n, 0:h]; float4 lanes, multi-row blocks
__global__ void k_stats(int n, int h) {
    int h4  = h >> 2;                 // 64 or 32
    int gpb = 256 / h4;               // 4 or 8 rows per block-iter
    int col = threadIdx.x % h4;
    int rof = threadIdx.x / h4;
    float4 s  = make_float4(0.f, 0.f, 0.f, 0.f);
    float4 ss = make_float4(0.f, 0.f, 0.f, 0.f);
    const float4* Y4 = (const float4*)g_Y;
    int stride = gridDim.x * gpb;
#pragma unroll 4
    for (int r = blockIdx.x * gpb + rof; r < n; r += stride) {
        float4 v = Y4[(size_t)r * h4 + col];
        s.x += v.x; s.y += v.y; s.z += v.z; s.w += v.w;
        ss.x = fmaf(v.x, v.x, ss.x);
        ss.y = fmaf(v.y, v.y, ss.y);
        ss.z = fmaf(v.z, v.z, ss.z);
        ss.w = fmaf(v.w, v.w, ss.w);
    }
    __shared__ float4 sh_s[256], sh_q[256];
    sh_s[threadIdx.x] = s;
    sh_q[threadIdx.x] = ss;
    __syncthreads();
    if (rof == 0) {
        for (int j = 1; j < gpb; j++) {
            float4 o = sh_s[j * h4 + col], q = sh_q[j * h4 + col];
            s.x += o.x; s.y += o.y; s.z += o.z; s.w += o.w;
            ss.x += q.x; ss.y += q.y; ss.z += q.z; ss.w += q.w;
        }
        int f = col << 2;
        atomicAdd(&g_S[f + 0], s.x);  atomicAdd(&g_S[f + 1], s.y);
        atomicAdd(&g_S[f + 2], s.z);  atomicAdd(&g_S[f + 3], s.w);
        atomicAdd(&g_SS[f + 0], ss.x); atomicAdd(&g_SS[f + 1], ss.y);
        atomicAdd(&g_SS[f + 2], ss.z); atomicAdd(&g_SS[f + 3], ss.w);
    }
}

__device__ __forceinline__ float bn1(float y, float s, float ss, float g, float b,
                                     float inv_n, bool act) {
    float mu  = s * inv_n;
    float var = ss * inv_n - mu * mu;
    float v = g * (y - mu) * rsqrtf(var + BN_EPS) + b;
    return act ? sp(v) : v;
}

template <bool ACT, bool COPY>
__global__ void k_apply(const float* __restrict__ gam, const float* __restrict__ bet,
                        int n, int h) {
    int i = blockIdx.x * blockDim.x + threadIdx.x;
    int total = n * (h / 4);
    if (i >= total) return;
    int f4 = i % (h / 4);
    float4 y  = ((const float4*)g_Y)[i];
    float4 S4 = ((const float4*)g_S)[f4];
    float4 Q4 = ((const float4*)g_SS)[f4];
    float4 G4 = __ldg((const float4*)gam + f4);
    float4 B4 = __ldg((const float4*)bet + f4);
    float inv_n = 1.f / (float)n;
    float4 o;
    o.x = bn1(y.x, S4.x, Q4.x, G4.x, B4.x, inv_n, ACT);
    o.y = bn1(y.y, S4.y, Q4.y, G4.y, B4.y, inv_n, ACT);
    o.z = bn1(y.z, S4.z, Q4.z, G4.z, B4.z, inv_n, ACT);
    o.w = bn1(y.w, S4.w, Q4.w, G4.w, B4.w, inv_n, ACT);
    ((float4*)g_X)[i] = o;
    if (COPY) ((float4*)g_Y)[i] = o;
}

__global__ void k_pool(const int* __restrict__ batch, int n) {
    int g = blockIdx.x;
    int f = threadIdx.x;
    __shared__ int slo, shi;
    if (f == 0) { slo = lb(batch, n, g); shi = lb(batch, n, g + 1); }
    __syncthreads();
    float s = 0.f;
    for (int r = slo; r < shi; r++) s += g_X[(size_t)r * HF + f];
    g_HG[g * HF + f] = s;
}

__global__ void k_hgw(const float* __restrict__ W1, const float* __restrict__ B1) {
    int g = blockIdx.x;
    int f = threadIdx.x;
    __shared__ float hg[HF];
    hg[f] = g_HG[g * HF + f];
    __syncthreads();
    float acc = __ldg(B1 + f);
#pragma unroll 8
    for (int k = 0; k < HF; k++)
        acc = fmaf(hg[k], __ldg(W1 + (size_t)(HF + k) * HF + f), acc);
    g_HGW[g * HF + f] = acc;
}

// ======== TF32 tensor-core GEMM: C[M,Nc] = A[M,K] @ W[K,Nc] + epilogue ========
// Block tile 128x64, BK=32. 8 warps in 4(m) x 2(n); warp tile 32x32.
// MODE 0: += g_HGW[batch[row]]; MODE 1: += bias[col];
// MODE 2: += bias[col], split write into two [M,64] halves of d_out.
#define APITCH 36
#define BPITCH 68
template <int MODE>
__global__ void __launch_bounds__(256)
k_gemm_tc(const float* __restrict__ A, const float* __restrict__ W,
          float* __restrict__ C, const float* __restrict__ bias,
          const int* __restrict__ batch, int M, int K, int Nc) {
    __shared__ uint32_t As[128 * APITCH];
    __shared__ uint32_t Bs[32 * BPITCH];

    int tid = threadIdx.x;
    int lane = tid & 31, warp = tid >> 5;
    int wm = warp & 3, wn = warp >> 2;
    int g = lane >> 2, t = lane & 3;
    int m0 = blockIdx.y * 128, n0 = blockIdx.x * 64;

    float acc[2][4][4];
#pragma unroll
    for (int i = 0; i < 2; i++)
#pragma unroll
        for (int j = 0; j < 4; j++)
#pragma unroll
            for (int k = 0; k < 4; k++) acc[i][j][k] = 0.f;

    // global-load coordinates
    int a_row[4], a_c4[4];
#pragma unroll
    for (int j = 0; j < 4; j++) {
        int idx = tid + j * 256;        // 0..1023 over 128x8 float4s
        a_row[j] = idx >> 3;
        a_c4[j]  = idx & 7;
    }
    int b_row[2], b_c4[2];
#pragma unroll
    for (int j = 0; j < 2; j++) {
        int idx = tid + j * 256;        // 0..511 over 32x16 float4s
        b_row[j] = idx >> 4;
        b_c4[j]  = idx & 15;
    }

    float4 pa[4], pb[2];
#pragma unroll
    for (int j = 0; j < 4; j++) {
        int r = m0 + a_row[j]; if (r >= M) r = M - 1;
        pa[j] = *(const float4*)(A + (size_t)r * K + (a_c4[j] << 2));
    }
#pragma unroll
    for (int j = 0; j < 2; j++)
        pb[j] = __ldg((const float4*)(W + (size_t)b_row[j] * Nc + n0 + (b_c4[j] << 2)));

    int ktiles = K >> 5;
    for (int kt = 0; kt < ktiles; kt++) {
        __syncthreads();
#pragma unroll
        for (int j = 0; j < 4; j++) {
            uint4 u = make_uint4(f2tf32(pa[j].x), f2tf32(pa[j].y),
                                 f2tf32(pa[j].z), f2tf32(pa[j].w));
            *(uint4*)&As[a_row[j] * APITCH + (a_c4[j] << 2)] = u;
        }
#pragma unroll
        for (int j = 0; j < 2; j++) {
            uint4 u = make_uint4(f2tf32(pb[j].x), f2tf32(pb[j].y),
                                 f2tf32(pb[j].z), f2tf32(pb[j].w));
            *(uint4*)&Bs[b_row[j] * BPITCH + (b_c4[j] << 2)] = u;
        }
        __syncthreads();

        if (kt + 1 < ktiles) {
            int ko = (kt + 1) << 5;
#pragma unroll
            for (int j = 0; j < 4; j++) {
                int r = m0 + a_row[j]; if (r >= M) r = M - 1;
                pa[j] = *(const float4*)(A + (size_t)r * K + ko + (a_c4[j] << 2));
            }
#pragma unroll
            for (int j = 0; j < 2; j++)
                pb[j] = __ldg((const float4*)(W + (size_t)(ko + b_row[j]) * Nc + n0 + (b_c4[j] << 2)));
        }

#pragma unroll
        for (int kk = 0; kk < 4; kk++) {
            int k8 = kk << 3;
            // PTX m16n8k8 A-fragment register order:
            //   a0=A[g][t]  a1=A[g+8][t]  a2=A[g][t+4]  a3=A[g+8][t+4]
            uint32_t af[2][4];
#pragma unroll
            for (int mt = 0; mt < 2; mt++) {
                int r = (wm << 5) + (mt << 4) + g;
                af[mt][0] = As[r * APITCH + k8 + t];
                af[mt][1] = As[(r + 8) * APITCH + k8 + t];
                af[mt][2] = As[r * APITCH + k8 + t + 4];
                af[mt][3] = As[(r + 8) * APITCH + k8 + t + 4];
            }
            uint32_t bf[4][2];
#pragma unroll
            for (int nt = 0; nt < 4; nt++) {
                int c = (wn << 5) + (nt << 3) + g;
                bf[nt][0] = Bs[(k8 + t) * BPITCH + c];
                bf[nt][1] = Bs[(k8 + t + 4) * BPITCH + c];
            }
#pragma unroll
            for (int mt = 0; mt < 2; mt++)
#pragma unroll
                for (int nt = 0; nt < 4; nt++)
                    mma_tf32(acc[mt][nt], af[mt][0], af[mt][1], af[mt][2], af[mt][3],
                             bf[nt][0], bf[nt][1]);
        }
    }

    // epilogue: c0=C[g][2t], c1=C[g][2t+1], c2=C[g+8][2t], c3=C[g+8][2t+1]
    int row_w = m0 + (wm << 5), col_w = n0 + (wn << 5);
#pragma unroll
    for (int mt = 0; mt < 2; mt++) {
#pragma unroll
        for (int half = 0; half < 2; half++) {
            int row = row_w + (mt << 4) + g + (half << 3);
            if (row >= M) continue;
            int bg = 0;
            if (MODE == 0) bg = __ldg(batch + row);
#pragma unroll
            for (int nt = 0; nt < 4; nt++) {
                int col = col_w + (nt << 3) + (t << 1);
                float v0 = acc[mt][nt][half * 2 + 0];
                float v1 = acc[mt][nt][half * 2 + 1];
                if (MODE == 0) {
                    float2 hw = *(const float2*)(g_HGW + (size_t)bg * HF + col);
                    v0 += hw.x; v1 += hw.y;
                    *(float2*)(C + (size_t)row * Nc + col) = make_float2(v0, v1);
                } else {
                    float2 b2 = *(const float2*)(bias + col);
                    v0 += b2.x; v1 += b2.y;
                    if (MODE == 1) {
                        *(float2*)(C + (size_t)row * Nc + col) = make_float2(v0, v1);
                    } else {
                        if (col < LATF)
                            *(float2*)(C + (size_t)row * LATF + col) = make_float2(v0, v1);
                        else
                            *(float2*)(C + (size_t)M * LATF + (size_t)row * LATF + (col - LATF))
                                = make_float2(v0, v1);
                    }
                }
            }
        }
    }
}

// ---------------- launch ----------------
extern "C" void kernel_launch(void* const* d_in, const int* in_sizes, int n_in,
                              void* d_out, int out_size) {
    const int*   node_type = (const int*)d_in[0];
    const int*   edge_type = (const int*)d_in[1];
    const int*   edge_index = (const int*)d_in[2];
    const int*   batch     = (const int*)d_in[3];
    const float* node_emb  = (const float*)d_in[4];
    const float* edge_emb  = (const float*)d_in[5];
    const float* g1 = (const float*)d_in[6],  *b1 = (const float*)d_in[7];
    const float* g2 = (const float*)d_in[8],  *b2 = (const float*)d_in[9];
    const float* g3 = (const float*)d_in[10], *b3 = (const float*)d_in[11];
    const float* go1 = (const float*)d_in[12], *bo1 = (const float*)d_in[13];
    const float* go2 = (const float*)d_in[14], *bo2 = (const float*)d_in[15];
    const float* W1 = (const float*)d_in[16], *B1 = (const float*)d_in[17];
    const float* W2 = (const float*)d_in[18], *B2 = (const float*)d_in[19];
    const float* W3 = (const float*)d_in[20], *B3 = (const float*)d_in[21];

    int N = in_sizes[0];
    int E = in_sizes[1];
    const int* src = edge_index;
    const int* dst = edge_index + E;

    float *pX, *pY;
    cudaGetSymbolAddress((void**)&pX, g_X);
    cudaGetSymbolAddress((void**)&pY, g_Y);

    const int TB = 256;
    int n_f4   = N * (HF / 4);
    int emb_gr = (n_f4 + TB - 1) / TB;
    int cv_gr  = ((E << 6) + TB - 1) / TB;
    int ap_gr256 = emb_gr;
    int ap_gr128 = (N * (128 / 4) + TB - 1) / TB;
    int gm = (N + 127) / 128;

    k_embed<<<emb_gr, TB>>>(node_type, node_emb, N);

    // --- layer 1 ---
    k_conv<<<cv_gr, TB>>>(src, dst, edge_type, edge_emb, E);
    k_zero_stats<<<1, HF>>>();
    k_stats<<<1024, 256>>>(N, HF);
    k_apply<true, true><<<ap_gr256, TB>>>(g1, b1, N, HF);

    // --- layer 2 ---
    k_conv<<<cv_gr, TB>>>(src, dst, edge_type, edge_emb, E);
    k_zero_stats<<<1, HF>>>();
    k_stats<<<1024, 256>>>(N, HF);
    k_apply<true, true><<<ap_gr256, TB>>>(g2, b2, N, HF);

    // --- layer 3 (no act) ---
    k_conv<<<cv_gr, TB>>>(src, dst, edge_type, edge_emb, E);
    k_zero_stats<<<1, HF>>>();
    k_stats<<<1024, 256>>>(N, HF);
    k_apply<false, false><<<ap_gr256, TB>>>(g3, b3, N, HF);

    // pooling + HGW = HG @ W1_bottom + B1
    k_pool<<<GFG, HF>>>(batch, N);
    k_hgw<<<GFG, HF>>>(W1, B1);

    // GEMM1: Y = X @ W1_top + HGW[batch]
    k_gemm_tc<0><<<dim3(HF / 64, gm), TB>>>(pX, W1, pY, nullptr, batch, N, HF, HF);
    k_zero_stats<<<1, HF>>>();
    k_stats<<<1024, 256>>>(N, HF);
    k_apply<true, false><<<ap_gr256, TB>>>(go1, bo1, N, HF);

    // GEMM2: Y = X @ W2 + B2 (Nc=128)
    k_gemm_tc<1><<<dim3(128 / 64, gm), TB>>>(pX, W2, pY, B2, nullptr, N, HF, 128);
    k_zero_stats<<<1, HF>>>();
    k_stats<<<1024, 256>>>(N, 128);
    k_apply<true, false><<<ap_gr128, TB>>>(go2, bo2, N, 128);

    // GEMM3: out = X @ W3 + B3, split (mu, logvar)
    k_gemm_tc<2><<<dim3(128 / 64, gm), TB>>>(pX, W3, (float*)d_out, B3, nullptr, N, 128, 128);

    (void)n_in; (void)out_size;
}

// round 4
// speedup vs baseline: 1.4239x; 1.2276x over previous
#include <cuda_runtime.h>
#include <cstdint>

// Problem constants: N=50000, E=300000, G=256, H=256, LAT=64
#define HF 256
#define GFG 256
#define LATF 64
#define NMAX 50000
#define EMAX 300000
#define BN_EPS 1e-5f

// ---- static scratch ----
__device__ __align__(128) float g_X[NMAX * HF];
__device__ __align__(128) float g_Y[NMAX * HF];
__device__ __align__(128) float g_HG[GFG * HF];
__device__ __align__(128) float g_HGW[GFG * HF];
__device__ float g_S[HF];
__device__ float g_SS[HF];
// CSR scratch
__device__ int g_deg[NMAX];
__device__ int g_rowptr[NMAX + 1];
__device__ int g_cursor[NMAX];
__device__ __align__(16) int2 g_epack[EMAX];   // (src, edge_type) sorted by dst

// ---------------- helpers ----------------
__device__ __forceinline__ float sp(float x) {
    // fast stable softplus: max(x,0) + log(1 + exp(-|x|)), abs err ~1e-7
    float t = __expf(-fabsf(x));
    return fmaxf(x, 0.f) + __logf(1.f + t);
}

__device__ __forceinline__ float4 sp4(float4 a, float4 b) {
    float4 r;
    r.x = sp(a.x + b.x);
    r.y = sp(a.y + b.y);
    r.z = sp(a.z + b.z);
    r.w = sp(a.w + b.w);
    return r;
}

__device__ __forceinline__ int lb(const int* __restrict__ a, int n, int key) {
    int lo = 0, hi = n;
    while (lo < hi) { int mid = (lo + hi) >> 1; if (a[mid] < key) lo = mid + 1; else hi = mid; }
    return lo;
}

__device__ __forceinline__ uint32_t f2tf32(float x) {
    uint32_t r;
    asm("cvt.rna.tf32.f32 %0, %1;" : "=r"(r) : "f"(x));
    return r;
}

__device__ __forceinline__ void mma_tf32(float c[4], uint32_t a0, uint32_t a1,
                                         uint32_t a2, uint32_t a3,
                                         uint32_t b0, uint32_t b1) {
    asm volatile(
        "mma.sync.aligned.m16n8k8.row.col.f32.tf32.tf32.f32 "
        "{%0,%1,%2,%3}, {%4,%5,%6,%7}, {%8,%9}, {%0,%1,%2,%3};"
        : "+f"(c[0]), "+f"(c[1]), "+f"(c[2]), "+f"(c[3])
        : "r"(a0), "r"(a1), "r"(a2), "r"(a3), "r"(b0), "r"(b1));
}

// ---------------- CSR build ----------------
__global__ void k_zero_deg(int n) {
    int i = blockIdx.x * blockDim.x + threadIdx.x;
    if (i < n) g_deg[i] = 0;
}

__global__ void k_hist(const int* __restrict__ dst, int e_cnt) {
    int e = blockIdx.x * blockDim.x + threadIdx.x;
    if (e < e_cnt) atomicAdd(&g_deg[dst[e]], 1);
}

__global__ void k_scan(int n) {
    __shared__ int sm[1024];
    int t = threadIdx.x;
    int chunk = (n + 1023) >> 10;
    int lo = t * chunk, hi = min(lo + chunk, n);
    int sum = 0;
    for (int i = lo; i < hi; i++) sum += g_deg[i];
    sm[t] = sum;
    __syncthreads();
    for (int off = 1; off < 1024; off <<= 1) {
        int v = (t >= off) ? sm[t - off] : 0;
        __syncthreads();
        sm[t] += v;
        __syncthreads();
    }
    int run = sm[t] - sum;   // exclusive prefix
    for (int i = lo; i < hi; i++) {
        g_rowptr[i] = run;
        g_cursor[i] = run;
        run += g_deg[i];
    }
    if (t == 1023) g_rowptr[n] = run;
}

__global__ void k_scatter(const int* __restrict__ src, const int* __restrict__ dst,
                          const int* __restrict__ et, int e_cnt) {
    int e = blockIdx.x * blockDim.x + threadIdx.x;
    if (e >= e_cnt) return;
    int pos = atomicAdd(&g_cursor[dst[e]], 1);
    g_epack[pos] = make_int2(src[e], et[e]);
}

// ---------------- core kernels ----------------

// X = node_emb[node_type]
__global__ void k_embed(const int* __restrict__ nt, const float* __restrict__ emb, int n) {
    int i = blockIdx.x * blockDim.x + threadIdx.x;
    int total = n * (HF / 4);
    if (i >= total) return;
    int node = i / (HF / 4);
    int f4   = i % (HF / 4);
    ((float4*)g_X)[i] = __ldg((const float4*)emb + (size_t)nt[node] * (HF / 4) + f4);
}

// Y[v] = X[v] + sum_{e: dst(e)=v} softplus(X[src(e)] + ew[et(e)])
// 32 lanes per node, 8 floats per lane; CSR, no atomics.
__global__ void __launch_bounds__(256) k_conv_csr(const float* __restrict__ ew, int n) {
    int grp = threadIdx.x >> 5;
    int lane = threadIdx.x & 31;
    int node = blockIdx.x * 8 + grp;
    if (node >= n) return;
    int lo = g_rowptr[node], hi = g_rowptr[node + 1];
    const float4* X4 = (const float4*)g_X;
    const float4* W4 = (const float4*)ew;
    int c = lane << 1;
    float4 a0 = X4[(size_t)node * 64 + c];
    float4 a1 = X4[(size_t)node * 64 + c + 1];
    for (int k = lo; k < hi; k++) {
        int2 se = __ldg(&g_epack[k]);
        const float4* xs = X4 + (size_t)se.x * 64 + c;
        const float4* ws = W4 + (size_t)se.y * 64 + c;
        float4 x0 = xs[0], x1 = xs[1];
        float4 w0 = __ldg(ws), w1 = __ldg(ws + 1);
        float4 m0 = sp4(x0, w0);
        float4 m1 = sp4(x1, w1);
        a0.x += m0.x; a0.y += m0.y; a0.z += m0.z; a0.w += m0.w;
        a1.x += m1.x; a1.y += m1.y; a1.z += m1.z; a1.w += m1.w;
    }
    float4* Y4 = (float4*)g_Y;
    Y4[(size_t)node * 64 + c] = a0;
    Y4[(size_t)node * 64 + c + 1] = a1;
}

__global__ void k_zero_stats() {
    g_S[threadIdx.x] = 0.f;
    g_SS[threadIdx.x] = 0.f;
}

// per-feature sum / sumsq of g_Y[0:n, 0:h]; MLP-8 front-batched loads
__global__ void __launch_bounds__(256) k_stats(int n, int h) {
    int h4  = h >> 2;                 // 64 or 32 (pow2)
    int gpb = 256 / h4;               // rows per block-iter
    int col = threadIdx.x & (h4 - 1);
    int rof = threadIdx.x / h4;
    int stride = gridDim.x * gpb;
    float4 s  = make_float4(0.f, 0.f, 0.f, 0.f);
    float4 ss = make_float4(0.f, 0.f, 0.f, 0.f);
    const float4* Y4 = (const float4*)g_Y;
    for (int base = blockIdx.x * gpb + rof; base < n; base += stride * 8) {
        float4 v[8];
#pragma unroll
        for (int j = 0; j < 8; j++) {
            int r = base + j * stride;
            v[j] = (r < n) ? Y4[(size_t)r * h4 + col] : make_float4(0.f, 0.f, 0.f, 0.f);
        }
#pragma unroll
        for (int j = 0; j < 8; j++) {
            s.x += v[j].x; s.y += v[j].y; s.z += v[j].z; s.w += v[j].w;
            ss.x = fmaf(v[j].x, v[j].x, ss.x);
            ss.y = fmaf(v[j].y, v[j].y, ss.y);
            ss.z = fmaf(v[j].z, v[j].z, ss.z);
            ss.w = fmaf(v[j].w, v[j].w, ss.w);
        }
    }
    __shared__ float4 sh_s[256], sh_q[256];
    sh_s[threadIdx.x] = s;
    sh_q[threadIdx.x] = ss;
    __syncthreads();
    if (rof == 0) {
        for (int j = 1; j < gpb; j++) {
            float4 o = sh_s[j * h4 + col], q = sh_q[j * h4 + col];
            s.x += o.x; s.y += o.y; s.z += o.z; s.w += o.w;
            ss.x += q.x; ss.y += q.y; ss.z += q.z; ss.w += q.w;
        }
        int f = col << 2;
        atomicAdd(&g_S[f + 0], s.x);  atomicAdd(&g_S[f + 1], s.y);
        atomicAdd(&g_S[f + 2], s.z);  atomicAdd(&g_S[f + 3], s.w);
        atomicAdd(&g_SS[f + 0], ss.x); atomicAdd(&g_SS[f + 1], ss.y);
        atomicAdd(&g_SS[f + 2], ss.z); atomicAdd(&g_SS[f + 3], ss.w);
    }
}

__device__ __forceinline__ float bn1(float y, float s, float ss, float g, float b,
                                     float inv_n, bool act) {
    float mu  = s * inv_n;
    float var = ss * inv_n - mu * mu;
    float v = g * (y - mu) * rsqrtf(var + BN_EPS) + b;
    return act ? sp(v) : v;
}

// X = (act?)BN(Y)
template <bool ACT>
__global__ void k_apply(const float* __restrict__ gam, const float* __restrict__ bet,
                        int n, int h) {
    int i = blockIdx.x * blockDim.x + threadIdx.x;
    int total = n * (h / 4);
    if (i >= total) return;
    int f4 = i % (h / 4);
    float4 y  = ((const float4*)g_Y)[i];
    float4 S4 = ((const float4*)g_S)[f4];
    float4 Q4 = ((const float4*)g_SS)[f4];
    float4 G4 = __ldg((const float4*)gam + f4);
    float4 B4 = __ldg((const float4*)bet + f4);
    float inv_n = 1.f / (float)n;
    float4 o;
    o.x = bn1(y.x, S4.x, Q4.x, G4.x, B4.x, inv_n, ACT);
    o.y = bn1(y.y, S4.y, Q4.y, G4.y, B4.y, inv_n, ACT);
    o.z = bn1(y.z, S4.z, Q4.z, G4.z, B4.z, inv_n, ACT);
    o.w = bn1(y.w, S4.w, Q4.w, G4.w, B4.w, inv_n, ACT);
    ((float4*)g_X)[i] = o;
}

__global__ void k_pool(const int* __restrict__ batch, int n) {
    int g = blockIdx.x;
    int f = threadIdx.x;
    __shared__ int slo, shi;
    if (f == 0) { slo = lb(batch, n, g); shi = lb(batch, n, g + 1); }
    __syncthreads();
    float s = 0.f;
    for (int r = slo; r < shi; r++) s += g_X[(size_t)r * HF + f];
    g_HG[g * HF + f] = s;
}

__global__ void k_hgw(const float* __restrict__ W1, const float* __restrict__ B1) {
    int g = blockIdx.x;
    int f = threadIdx.x;
    __shared__ float hg[HF];
    hg[f] = g_HG[g * HF + f];
    __syncthreads();
    float acc = __ldg(B1 + f);
#pragma unroll 8
    for (int k = 0; k < HF; k++)
        acc = fmaf(hg[k], __ldg(W1 + (size_t)(HF + k) * HF + f), acc);
    g_HGW[g * HF + f] = acc;
}

// ======== TF32 tensor-core GEMM: C[M,Nc] = A[M,K] @ W[K,Nc] + epilogue ========
#define APITCH 36
#define BPITCH 68
template <int MODE>
__global__ void __launch_bounds__(256)
k_gemm_tc(const float* __restrict__ A, const float* __restrict__ W,
          float* __restrict__ C, const float* __restrict__ bias,
          const int* __restrict__ batch, int M, int K, int Nc) {
    __shared__ uint32_t As[128 * APITCH];
    __shared__ uint32_t Bs[32 * BPITCH];

    int tid = threadIdx.x;
    int lane = tid & 31, warp = tid >> 5;
    int wm = warp & 3, wn = warp >> 2;
    int g = lane >> 2, t = lane & 3;
    int m0 = blockIdx.y * 128, n0 = blockIdx.x * 64;

    float acc[2][4][4];
#pragma unroll
    for (int i = 0; i < 2; i++)
#pragma unroll
        for (int j = 0; j < 4; j++)
#pragma unroll
            for (int k = 0; k < 4; k++) acc[i][j][k] = 0.f;

    int a_row[4], a_c4[4];
#pragma unroll
    for (int j = 0; j < 4; j++) {
        int idx = tid + j * 256;
        a_row[j] = idx >> 3;
        a_c4[j]  = idx & 7;
    }
    int b_row[2], b_c4[2];
#pragma unroll
    for (int j = 0; j < 2; j++) {
        int idx = tid + j * 256;
        b_row[j] = idx >> 4;
        b_c4[j]  = idx & 15;
    }

    float4 pa[4], pb[2];
#pragma unroll
    for (int j = 0; j < 4; j++) {
        int r = m0 + a_row[j]; if (r >= M) r = M - 1;
        pa[j] = *(const float4*)(A + (size_t)r * K + (a_c4[j] << 2));
    }
#pragma unroll
    for (int j = 0; j < 2; j++)
        pb[j] = __ldg((const float4*)(W + (size_t)b_row[j] * Nc + n0 + (b_c4[j] << 2)));

    int ktiles = K >> 5;
    for (int kt = 0; kt < ktiles; kt++) {
        __syncthreads();
#pragma unroll
        for (int j = 0; j < 4; j++) {
            uint4 u = make_uint4(f2tf32(pa[j].x), f2tf32(pa[j].y),
                                 f2tf32(pa[j].z), f2tf32(pa[j].w));
            *(uint4*)&As[a_row[j] * APITCH + (a_c4[j] << 2)] = u;
        }
#pragma unroll
        for (int j = 0; j < 2; j++) {
            uint4 u = make_uint4(f2tf32(pb[j].x), f2tf32(pb[j].y),
                                 f2tf32(pb[j].z), f2tf32(pb[j].w));
            *(uint4*)&Bs[b_row[j] * BPITCH + (b_c4[j] << 2)] = u;
        }
        __syncthreads();

        if (kt + 1 < ktiles) {
            int ko = (kt + 1) << 5;
#pragma unroll
            for (int j = 0; j < 4; j++) {
                int r = m0 + a_row[j]; if (r >= M) r = M - 1;
                pa[j] = *(const float4*)(A + (size_t)r * K + ko + (a_c4[j] << 2));
            }
#pragma unroll
            for (int j = 0; j < 2; j++)
                pb[j] = __ldg((const float4*)(W + (size_t)(ko + b_row[j]) * Nc + n0 + (b_c4[j] << 2)));
        }

#pragma unroll
        for (int kk = 0; kk < 4; kk++) {
            int k8 = kk << 3;
            // A-frag order: a0=A[g][t] a1=A[g+8][t] a2=A[g][t+4] a3=A[g+8][t+4]
            uint32_t af[2][4];
#pragma unroll
            for (int mt = 0; mt < 2; mt++) {
                int r = (wm << 5) + (mt << 4) + g;
                af[mt][0] = As[r * APITCH + k8 + t];
                af[mt][1] = As[(r + 8) * APITCH + k8 + t];
                af[mt][2] = As[r * APITCH + k8 + t + 4];
                af[mt][3] = As[(r + 8) * APITCH + k8 + t + 4];
            }
            uint32_t bf[4][2];
#pragma unroll
            for (int nt = 0; nt < 4; nt++) {
                int c = (wn << 5) + (nt << 3) + g;
                bf[nt][0] = Bs[(k8 + t) * BPITCH + c];
                bf[nt][1] = Bs[(k8 + t + 4) * BPITCH + c];
            }
#pragma unroll
            for (int mt = 0; mt < 2; mt++)
#pragma unroll
                for (int nt = 0; nt < 4; nt++)
                    mma_tf32(acc[mt][nt], af[mt][0], af[mt][1], af[mt][2], af[mt][3],
                             bf[nt][0], bf[nt][1]);
        }
    }

    int row_w = m0 + (wm << 5), col_w = n0 + (wn << 5);
#pragma unroll
    for (int mt = 0; mt < 2; mt++) {
#pragma unroll
        for (int half = 0; half < 2; half++) {
            int row = row_w + (mt << 4) + g + (half << 3);
            if (row >= M) continue;
            int bg = 0;
            if (MODE == 0) bg = __ldg(batch + row);
#pragma unroll
            for (int nt = 0; nt < 4; nt++) {
                int col = col_w + (nt << 3) + (t << 1);
                float v0 = acc[mt][nt][half * 2 + 0];
                float v1 = acc[mt][nt][half * 2 + 1];
                if (MODE == 0) {
                    float2 hw = *(const float2*)(g_HGW + (size_t)bg * HF + col);
                    v0 += hw.x; v1 += hw.y;
                    *(float2*)(C + (size_t)row * Nc + col) = make_float2(v0, v1);
                } else {
                    float2 b2 = *(const float2*)(bias + col);
                    v0 += b2.x; v1 += b2.y;
                    if (MODE == 1) {
                        *(float2*)(C + (size_t)row * Nc + col) = make_float2(v0, v1);
                    } else {
                        if (col < LATF)
                            *(float2*)(C + (size_t)row * LATF + col) = make_float2(v0, v1);
                        else
                            *(float2*)(C + (size_t)M * LATF + (size_t)row * LATF + (col - LATF))
                                = make_float2(v0, v1);
                    }
                }
            }
        }
    }
}

// ---------------- launch ----------------
extern "C" void kernel_launch(void* const* d_in, const int* in_sizes, int n_in,
                              void* d_out, int out_size) {
    const int*   node_type = (const int*)d_in[0];
    const int*   edge_type = (const int*)d_in[1];
    const int*   edge_index = (const int*)d_in[2];
    const int*   batch     = (const int*)d_in[3];
    const float* node_emb  = (const float*)d_in[4];
    const float* edge_emb  = (const float*)d_in[5];
    const float* g1 = (const float*)d_in[6],  *b1 = (const float*)d_in[7];
    const float* g2 = (const float*)d_in[8],  *b2 = (const float*)d_in[9];
    const float* g3 = (const float*)d_in[10], *b3 = (const float*)d_in[11];
    const float* go1 = (const float*)d_in[12], *bo1 = (const float*)d_in[13];
    const float* go2 = (const float*)d_in[14], *bo2 = (const float*)d_in[15];
    const float* W1 = (const float*)d_in[16], *B1 = (const float*)d_in[17];
    const float* W2 = (const float*)d_in[18], *B2 = (const float*)d_in[19];
    const float* W3 = (const float*)d_in[20], *B3 = (const float*)d_in[21];

    int N = in_sizes[0];
    int E = in_sizes[1];
    const int* src = edge_index;
    const int* dst = edge_index + E;

    float *pX, *pY;
    cudaGetSymbolAddress((void**)&pX, g_X);
    cudaGetSymbolAddress((void**)&pY, g_Y);

    const int TB = 256;
    int emb_gr = (N * (HF / 4) + TB - 1) / TB;
    int ap_gr256 = emb_gr;
    int ap_gr128 = (N * (128 / 4) + TB - 1) / TB;
    int gm = (N + 127) / 128;
    int cv_gr = (N + 7) / 8;
    int e_gr = (E + TB - 1) / TB;
    int n_gr = (N + TB - 1) / TB;

    // ---- CSR build (sort edges by dst) ----
    k_zero_deg<<<n_gr, TB>>>(N);
    k_hist<<<e_gr, TB>>>(dst, E);
    k_scan<<<1, 1024>>>(N);
    k_scatter<<<e_gr, TB>>>(src, dst, edge_type, E);

    // embed
    k_embed<<<emb_gr, TB>>>(node_type, node_emb, N);

    // --- layer 1 ---
    k_conv_csr<<<cv_gr, TB>>>(edge_emb, N);
    k_zero_stats<<<1, HF>>>();
    k_stats<<<1024, 256>>>(N, HF);
    k_apply<true><<<ap_gr256, TB>>>(g1, b1, N, HF);

    // --- layer 2 ---
    k_conv_csr<<<cv_gr, TB>>>(edge_emb, N);
    k_zero_stats<<<1, HF>>>();
    k_stats<<<1024, 256>>>(N, HF);
    k_apply<true><<<ap_gr256, TB>>>(g2, b2, N, HF);

    // --- layer 3 (no act) ---
    k_conv_csr<<<cv_gr, TB>>>(edge_emb, N);
    k_zero_stats<<<1, HF>>>();
    k_stats<<<1024, 256>>>(N, HF);
    k_apply<false><<<ap_gr256, TB>>>(g3, b3, N, HF);

    // pooling + HGW = HG @ W1_bottom + B1
    k_pool<<<GFG, HF>>>(batch, N);
    k_hgw<<<GFG, HF>>>(W1, B1);

    // GEMM1: Y = X @ W1_top + HGW[batch]
    k_gemm_tc<0><<<dim3(HF / 64, gm), TB>>>(pX, W1, pY, nullptr, batch, N, HF, HF);
    k_zero_stats<<<1, HF>>>();
    k_stats<<<1024, 256>>>(N, HF);
    k_apply<true><<<ap_gr256, TB>>>(go1, bo1, N, HF);

    // GEMM2: Y = X @ W2 + B2 (Nc=128)
    k_gemm_tc<1><<<dim3(128 / 64, gm), TB>>>(pX, W2, pY, B2, nullptr, N, HF, 128);
    k_zero_stats<<<1, HF>>>();
    k_stats<<<1024, 256>>>(N, 128);
    k_apply<true><<<ap_gr128, TB>>>(go2, bo2, N, 128);

    // GEMM3: out = X @ W3 + B3, split (mu, logvar)
    k_gemm_tc<2><<<dim3(128 / 64, gm), TB>>>(pX, W3, (float*)d_out, B3, nullptr, N, 128, 128);

    (void)n_in; (void)out_size;
}

// round 5
// speedup vs baseline: 1.4271x; 1.0023x over previous
#include <cuda_runtime.h>
#include <cstdint>

// Problem constants: N=50000, E=300000, G=256, H=256, LAT=64
#define HF 256
#define GFG 256
#define LATF 64
#define NMAX 50000
#define EMAX 300000
#define BN_EPS 1e-5f

// ---- static scratch ----
__device__ __align__(128) float g_X[NMAX * HF];
__device__ __align__(128) float g_Y[NMAX * HF];
__device__ __align__(128) float g_HG[GFG * HF];
__device__ __align__(128) float g_HGW[GFG * HF];
__device__ __align__(16) float g_S[HF];
__device__ __align__(16) float g_SS[HF];
__device__ __align__(16) float g_scale[HF];
__device__ __align__(16) float g_shift[HF];
// CSR scratch
__device__ int g_deg[NMAX];
__device__ int g_rowptr[NMAX + 1];
__device__ int g_cursor[NMAX];
__device__ __align__(16) int2 g_epack[EMAX];   // (src, edge_type) sorted by dst

// ---------------- helpers ----------------
__device__ __forceinline__ float sp(float x) {
    float t = __expf(-fabsf(x));
    return fmaxf(x, 0.f) + __logf(1.f + t);
}

__device__ __forceinline__ float4 sp4(float4 a, float4 b) {
    float4 r;
    r.x = sp(a.x + b.x);
    r.y = sp(a.y + b.y);
    r.z = sp(a.z + b.z);
    r.w = sp(a.w + b.w);
    return r;
}

__device__ __forceinline__ int lb(const int* __restrict__ a, int n, int key) {
    int lo = 0, hi = n;
    while (lo < hi) { int mid = (lo + hi) >> 1; if (a[mid] < key) lo = mid + 1; else hi = mid; }
    return lo;
}

__device__ __forceinline__ uint32_t f2tf32(float x) {
    uint32_t r;
    asm("cvt.rna.tf32.f32 %0, %1;" : "=r"(r) : "f"(x));
    return r;
}

__device__ __forceinline__ void mma_tf32(float c[4], uint32_t a0, uint32_t a1,
                                         uint32_t a2, uint32_t a3,
                                         uint32_t b0, uint32_t b1) {
    asm volatile(
        "mma.sync.aligned.m16n8k8.row.col.f32.tf32.tf32.f32 "
        "{%0,%1,%2,%3}, {%4,%5,%6,%7}, {%8,%9}, {%0,%1,%2,%3};"
        : "+f"(c[0]), "+f"(c[1]), "+f"(c[2]), "+f"(c[3])
        : "r"(a0), "r"(a1), "r"(a2), "r"(a3), "r"(b0), "r"(b1));
}

// ---------------- CSR build ----------------
__global__ void k_zero_deg(int n) {
    int i = blockIdx.x * blockDim.x + threadIdx.x;
    if (i < n) g_deg[i] = 0;
}

__global__ void k_hist(const int* __restrict__ dst, int e_cnt) {
    int e = blockIdx.x * blockDim.x + threadIdx.x;
    if (e < e_cnt) atomicAdd(&g_deg[dst[e]], 1);
}

__global__ void k_scan(int n) {
    __shared__ int sm[1024];
    int t = threadIdx.x;
    int chunk = (n + 1023) >> 10;
    int lo = t * chunk, hi = min(lo + chunk, n);
    int sum = 0;
    for (int i = lo; i < hi; i++) sum += g_deg[i];
    sm[t] = sum;
    __syncthreads();
    for (int off = 1; off < 1024; off <<= 1) {
        int v = (t >= off) ? sm[t - off] : 0;
        __syncthreads();
        sm[t] += v;
        __syncthreads();
    }
    int run = sm[t] - sum;
    for (int i = lo; i < hi; i++) {
        g_rowptr[i] = run;
        g_cursor[i] = run;
        run += g_deg[i];
    }
    if (t == 1023) g_rowptr[n] = run;
}

__global__ void k_scatter(const int* __restrict__ src, const int* __restrict__ dst,
                          const int* __restrict__ et, int e_cnt) {
    int e = blockIdx.x * blockDim.x + threadIdx.x;
    if (e >= e_cnt) return;
    int pos = atomicAdd(&g_cursor[dst[e]], 1);
    g_epack[pos] = make_int2(src[e], et[e]);
}

// ---------------- core kernels ----------------

__global__ void k_embed(const int* __restrict__ nt, const float* __restrict__ emb, int n) {
    int i = blockIdx.x * blockDim.x + threadIdx.x;
    int total = n * (HF / 4);
    if (i >= total) return;
    int node = i / (HF / 4);
    int f4   = i % (HF / 4);
    ((float4*)g_X)[i] = __ldg((const float4*)emb + (size_t)nt[node] * (HF / 4) + f4);
}

__global__ void k_zero_stats() {
    g_S[threadIdx.x] = 0.f;
    g_SS[threadIdx.x] = 0.f;
}

// Y[v] = X[v] + sum softplus(X[src]+ew[et]); fused per-feature stats accumulation
__global__ void __launch_bounds__(256) k_conv_csr(const float* __restrict__ ew, int n) {
    __shared__ float smS[HF], smQ[HF];
    smS[threadIdx.x] = 0.f;
    smQ[threadIdx.x] = 0.f;
    __syncthreads();

    int grp = threadIdx.x >> 5;
    int lane = threadIdx.x & 31;
    int node = blockIdx.x * 8 + grp;
    if (node < n) {
        int lo = g_rowptr[node], hi = g_rowptr[node + 1];
        const float4* X4 = (const float4*)g_X;
        const float4* W4 = (const float4*)ew;
        int c = lane << 1;
        float4 a0 = X4[(size_t)node * 64 + c];
        float4 a1 = X4[(size_t)node * 64 + c + 1];
        for (int k = lo; k < hi; k++) {
            int2 se = __ldg(&g_epack[k]);
            const float4* xs = X4 + (size_t)se.x * 64 + c;
            const float4* ws = W4 + (size_t)se.y * 64 + c;
            float4 x0 = xs[0], x1 = xs[1];
            float4 w0 = __ldg(ws), w1 = __ldg(ws + 1);
            float4 m0 = sp4(x0, w0);
            float4 m1 = sp4(x1, w1);
            a0.x += m0.x; a0.y += m0.y; a0.z += m0.z; a0.w += m0.w;
            a1.x += m1.x; a1.y += m1.y; a1.z += m1.z; a1.w += m1.w;
        }
        float4* Y4 = (float4*)g_Y;
        Y4[(size_t)node * 64 + c] = a0;
        Y4[(size_t)node * 64 + c + 1] = a1;
        int f = lane << 3;
        atomicAdd(&smS[f + 0], a0.x); atomicAdd(&smQ[f + 0], a0.x * a0.x);
        atomicAdd(&smS[f + 1], a0.y); atomicAdd(&smQ[f + 1], a0.y * a0.y);
        atomicAdd(&smS[f + 2], a0.z); atomicAdd(&smQ[f + 2], a0.z * a0.z);
        atomicAdd(&smS[f + 3], a0.w); atomicAdd(&smQ[f + 3], a0.w * a0.w);
        atomicAdd(&smS[f + 4], a1.x); atomicAdd(&smQ[f + 4], a1.x * a1.x);
        atomicAdd(&smS[f + 5], a1.y); atomicAdd(&smQ[f + 5], a1.y * a1.y);
        atomicAdd(&smS[f + 6], a1.z); atomicAdd(&smQ[f + 6], a1.z * a1.z);
        atomicAdd(&smS[f + 7], a1.w); atomicAdd(&smQ[f + 7], a1.w * a1.w);
    }
    __syncthreads();
    atomicAdd(&g_S[threadIdx.x], smS[threadIdx.x]);
    atomicAdd(&g_SS[threadIdx.x], smQ[threadIdx.x]);
}

// (scale,shift) from (S,SS,gamma,beta); re-zero S/SS for next layer
__global__ void k_coef(const float* __restrict__ gam, const float* __restrict__ bet,
                       float inv_n, int h) {
    int f = threadIdx.x;
    if (f < h) {
        float s = g_S[f], q = g_SS[f];
        float mu  = s * inv_n;
        float var = q * inv_n - mu * mu;
        float sc = __ldg(gam + f) * rsqrtf(var + BN_EPS);
        g_scale[f] = sc;
        g_shift[f] = __ldg(bet + f) - mu * sc;
        g_S[f] = 0.f;
        g_SS[f] = 0.f;
    }
}

// X = act(scale*Y + shift)   (for conv layers 1,2 only)
template <bool ACT>
__global__ void k_apply_coef(int n, int h) {
    int i = blockIdx.x * blockDim.x + threadIdx.x;
    int total = n * (h / 4);
    if (i >= total) return;
    int f4 = i % (h / 4);
    float4 y  = ((const float4*)g_Y)[i];
    float4 sc = ((const float4*)g_scale)[f4];
    float4 sh = ((const float4*)g_shift)[f4];
    float4 o;
    o.x = fmaf(y.x, sc.x, sh.x);
    o.y = fmaf(y.y, sc.y, sh.y);
    o.z = fmaf(y.z, sc.z, sh.z);
    o.w = fmaf(y.w, sc.w, sh.w);
    if (ACT) { o.x = sp(o.x); o.y = sp(o.y); o.z = sp(o.z); o.w = sp(o.w); }
    ((float4*)g_X)[i] = o;
}

// HG[g][f] = sum over nodes of bn(Y) = scale[f]*sum(Y) + cnt*shift[f]
__global__ void k_pool(const int* __restrict__ batch, int n) {
    int g = blockIdx.x;
    int f = threadIdx.x;
    __shared__ int slo, shi;
    if (f == 0) { slo = lb(batch, n, g); shi = lb(batch, n, g + 1); }
    __syncthreads();
    float s = 0.f;
    for (int r = slo; r < shi; r++) s += g_Y[(size_t)r * HF + f];
    g_HG[g * HF + f] = g_scale[f] * s + (float)(shi - slo) * g_shift[f];
}

__global__ void k_hgw(const float* __restrict__ W1, const float* __restrict__ B1) {
    int g = blockIdx.x;
    int f = threadIdx.x;
    __shared__ float hg[HF];
    hg[f] = g_HG[g * HF + f];
    __syncthreads();
    float acc = __ldg(B1 + f);
#pragma unroll 8
    for (int k = 0; k < HF; k++)
        acc = fmaf(hg[k], __ldg(W1 + (size_t)(HF + k) * HF + f), acc);
    g_HGW[g * HF + f] = acc;
}

// ======== TF32 tensor-core GEMM with fused BN-affine on A and fused output stats ====
// MODE 0: += g_HGW[batch[row]]; MODE 1: += bias[col]; MODE 2: bias + split-write d_out.
// AFF 0: raw A; 1: scale*a+shift; 2: softplus(scale*a+shift).
#define APITCH 36
#define BPITCH 68
template <int MODE, int AFF, bool STATS>
__global__ void __launch_bounds__(256)
k_gemm_tc(const float* __restrict__ A, const float* __restrict__ W,
          float* __restrict__ C, const float* __restrict__ bias,
          const int* __restrict__ batch, int M, int K, int Nc) {
    __shared__ uint32_t As[128 * APITCH];
    __shared__ uint32_t Bs[32 * BPITCH];
    __shared__ float smS[64], smQ[64];

    int tid = threadIdx.x;
    int lane = tid & 31, warp = tid >> 5;
    int wm = warp & 3, wn = warp >> 2;
    int g = lane >> 2, t = lane & 3;
    int m0 = blockIdx.y * 128, n0 = blockIdx.x * 64;

    if (STATS && tid < 64) { smS[tid] = 0.f; smQ[tid] = 0.f; }

    float acc[2][4][4];
#pragma unroll
    for (int i = 0; i < 2; i++)
#pragma unroll
        for (int j = 0; j < 4; j++)
#pragma unroll
            for (int k = 0; k < 4; k++) acc[i][j][k] = 0.f;

    int a_row[4], a_c4[4];
#pragma unroll
    for (int j = 0; j < 4; j++) {
        int idx = tid + j * 256;
        a_row[j] = idx >> 3;
        a_c4[j]  = idx & 7;
    }
    int b_row[2], b_c4[2];
#pragma unroll
    for (int j = 0; j < 2; j++) {
        int idx = tid + j * 256;
        b_row[j] = idx >> 4;
        b_c4[j]  = idx & 15;
    }

    // A load with fused affine(+act); kc = k-column base of the 4 loaded floats
    auto loadA = [&](int r, int kc) -> float4 {
        float4 v = *(const float4*)(A + (size_t)r * K + kc);
        if (AFF >= 1) {
            float4 sc = *(const float4*)(g_scale + kc);
            float4 sh = *(const float4*)(g_shift + kc);
            v.x = fmaf(v.x, sc.x, sh.x);
            v.y = fmaf(v.y, sc.y, sh.y);
            v.z = fmaf(v.z, sc.z, sh.z);
            v.w = fmaf(v.w, sc.w, sh.w);
            if (AFF == 2) { v.x = sp(v.x); v.y = sp(v.y); v.z = sp(v.z); v.w = sp(v.w); }
        }
        return v;
    };

    float4 pa[4], pb[2];
#pragma unroll
    for (int j = 0; j < 4; j++) {
        int r = m0 + a_row[j]; if (r >= M) r = M - 1;
        pa[j] = loadA(r, a_c4[j] << 2);
    }
#pragma unroll
    for (int j = 0; j < 2; j++)
        pb[j] = __ldg((const float4*)(W + (size_t)b_row[j] * Nc + n0 + (b_c4[j] << 2)));

    int ktiles = K >> 5;
    for (int kt = 0; kt < ktiles; kt++) {
        __syncthreads();
#pragma unroll
        for (int j = 0; j < 4; j++) {
            uint4 u = make_uint4(f2tf32(pa[j].x), f2tf32(pa[j].y),
                                 f2tf32(pa[j].z), f2tf32(pa[j].w));
            *(uint4*)&As[a_row[j] * APITCH + (a_c4[j] << 2)] = u;
        }
#pragma unroll
        for (int j = 0; j < 2; j++) {
            uint4 u = make_uint4(f2tf32(pb[j].x), f2tf32(pb[j].y),
                                 f2tf32(pb[j].z), f2tf32(pb[j].w));
            *(uint4*)&Bs[b_row[j] * BPITCH + (b_c4[j] << 2)] = u;
        }
        __syncthreads();

        if (kt + 1 < ktiles) {
            int ko = (kt + 1) << 5;
#pragma unroll
            for (int j = 0; j < 4; j++) {
                int r = m0 + a_row[j]; if (r >= M) r = M - 1;
                pa[j] = loadA(r, ko + (a_c4[j] << 2));
            }
#pragma unroll
            for (int j = 0; j < 2; j++)
                pb[j] = __ldg((const float4*)(W + (size_t)(ko + b_row[j]) * Nc + n0 + (b_c4[j] << 2)));
        }

#pragma unroll
        for (int kk = 0; kk < 4; kk++) {
            int k8 = kk << 3;
            uint32_t af[2][4];
#pragma unroll
            for (int mt = 0; mt < 2; mt++) {
                int r = (wm << 5) + (mt << 4) + g;
                af[mt][0] = As[r * APITCH + k8 + t];
                af[mt][1] = As[(r + 8) * APITCH + k8 + t];
                af[mt][2] = As[r * APITCH + k8 + t + 4];
                af[mt][3] = As[(r + 8) * APITCH + k8 + t + 4];
            }
            uint32_t bf[4][2];
#pragma unroll
            for (int nt = 0; nt < 4; nt++) {
                int c = (wn << 5) + (nt << 3) + g;
                bf[nt][0] = Bs[(k8 + t) * BPITCH + c];
                bf[nt][1] = Bs[(k8 + t + 4) * BPITCH + c];
            }
#pragma unroll
            for (int mt = 0; mt < 2; mt++)
#pragma unroll
                for (int nt = 0; nt < 4; nt++)
                    mma_tf32(acc[mt][nt], af[mt][0], af[mt][1], af[mt][2], af[mt][3],
                             bf[nt][0], bf[nt][1]);
        }
    }

    // ---- epilogue (+ optional per-column stats) ----
    float csum[8], csq[8];
#pragma unroll
    for (int j = 0; j < 8; j++) { csum[j] = 0.f; csq[j] = 0.f; }

    int row_w = m0 + (wm << 5), col_w = n0 + (wn << 5);
#pragma unroll
    for (int mt = 0; mt < 2; mt++) {
#pragma unroll
        for (int half = 0; half < 2; half++) {
            int row = row_w + (mt << 4) + g + (half << 3);
            if (row >= M) continue;
            int bg = 0;
            if (MODE == 0) bg = __ldg(batch + row);
#pragma unroll
            for (int nt = 0; nt < 4; nt++) {
                int col = col_w + (nt << 3) + (t << 1);
                float v0 = acc[mt][nt][half * 2 + 0];
                float v1 = acc[mt][nt][half * 2 + 1];
                if (MODE == 0) {
                    float2 hw = *(const float2*)(g_HGW + (size_t)bg * HF + col);
                    v0 += hw.x; v1 += hw.y;
                    *(float2*)(C + (size_t)row * Nc + col) = make_float2(v0, v1);
                } else {
                    float2 b2 = *(const float2*)(bias + col);
                    v0 += b2.x; v1 += b2.y;
                    if (MODE == 1) {
                        *(float2*)(C + (size_t)row * Nc + col) = make_float2(v0, v1);
                    } else {
                        if (col < LATF)
                            *(float2*)(C + (size_t)row * LATF + col) = make_float2(v0, v1);
                        else
                            *(float2*)(C + (size_t)M * LATF + (size_t)row * LATF + (col - LATF))
                                = make_float2(v0, v1);
                    }
                }
                if (STATS) {
                    int j = nt * 2;
                    csum[j]     += v0; csq[j]     = fmaf(v0, v0, csq[j]);
                    csum[j + 1] += v1; csq[j + 1] = fmaf(v1, v1, csq[j + 1]);
                }
            }
        }
    }

    if (STATS) {
#pragma unroll
        for (int j = 0; j < 8; j++) {
            csum[j] += __shfl_xor_sync(0xffffffffu, csum[j], 4);
            csum[j] += __shfl_xor_sync(0xffffffffu, csum[j], 8);
            csum[j] += __shfl_xor_sync(0xffffffffu, csum[j], 16);
            csq[j]  += __shfl_xor_sync(0xffffffffu, csq[j], 4);
            csq[j]  += __shfl_xor_sync(0xffffffffu, csq[j], 8);
            csq[j]  += __shfl_xor_sync(0xffffffffu, csq[j], 16);
        }
        if (g == 0) {  // lanes 0..3
#pragma unroll
            for (int j = 0; j < 8; j++) {
                int lc = (wn << 5) + ((j >> 1) << 3) + (t << 1) + (j & 1);
                atomicAdd(&smS[lc], csum[j]);
                atomicAdd(&smQ[lc], csq[j]);
            }
        }
        __syncthreads();
        if (tid < 64) {
            atomicAdd(&g_S[n0 + tid], smS[tid]);
            atomicAdd(&g_SS[n0 + tid], smQ[tid]);
        }
    }
}

// ---------------- launch ----------------
extern "C" void kernel_launch(void* const* d_in, const int* in_sizes, int n_in,
                              void* d_out, int out_size) {
    const int*   node_type = (const int*)d_in[0];
    const int*   edge_type = (const int*)d_in[1];
    const int*   edge_index = (const int*)d_in[2];
    const int*   batch     = (const int*)d_in[3];
    const float* node_emb  = (const float*)d_in[4];
    const float* edge_emb  = (const float*)d_in[5];
    const float* g1 = (const float*)d_in[6],  *b1 = (const float*)d_in[7];
    const float* g2 = (const float*)d_in[8],  *b2 = (const float*)d_in[9];
    const float* g3 = (const float*)d_in[10], *b3 = (const float*)d_in[11];
    const float* go1 = (const float*)d_in[12], *bo1 = (const float*)d_in[13];
    const float* go2 = (const float*)d_in[14], *bo2 = (const float*)d_in[15];
    const float* W1 = (const float*)d_in[16], *B1 = (const float*)d_in[17];
    const float* W2 = (const float*)d_in[18], *B2 = (const float*)d_in[19];
    const float* W3 = (const float*)d_in[20], *B3 = (const float*)d_in[21];

    int N = in_sizes[0];
    int E = in_sizes[1];
    const int* src = edge_index;
    const int* dst = edge_index + E;

    float *pX, *pY;
    cudaGetSymbolAddress((void**)&pX, g_X);
    cudaGetSymbolAddress((void**)&pY, g_Y);

    const int TB = 256;
    float inv_n = 1.f / (float)N;
    int emb_gr = (N * (HF / 4) + TB - 1) / TB;
    int ap_gr256 = emb_gr;
    int gm = (N + 127) / 128;
    int cv_gr = (N + 7) / 8;
    int e_gr = (E + TB - 1) / TB;
    int n_gr = (N + TB - 1) / TB;

    // ---- CSR build ----
    k_zero_deg<<<n_gr, TB>>>(N);
    k_hist<<<e_gr, TB>>>(dst, E);
    k_scan<<<1, 1024>>>(N);
    k_scatter<<<e_gr, TB>>>(src, dst, edge_type, E);

    k_embed<<<emb_gr, TB>>>(node_type, node_emb, N);
    k_zero_stats<<<1, HF>>>();

    // --- layer 1 ---
    k_conv_csr<<<cv_gr, TB>>>(edge_emb, N);           // Y + stats
    k_coef<<<1, HF>>>(g1, b1, inv_n, HF);
    k_apply_coef<true><<<ap_gr256, TB>>>(N, HF);      // X = act(bn(Y))

    // --- layer 2 ---
    k_conv_csr<<<cv_gr, TB>>>(edge_emb, N);
    k_coef<<<1, HF>>>(g2, b2, inv_n, HF);
    k_apply_coef<true><<<ap_gr256, TB>>>(N, HF);

    // --- layer 3 (no act; BN fused into pool & GEMM1 A-load) ---
    k_conv_csr<<<cv_gr, TB>>>(edge_emb, N);
    k_coef<<<1, HF>>>(g3, b3, inv_n, HF);

    // pooling (affine inline) + HGW
    k_pool<<<GFG, HF>>>(batch, N);
    k_hgw<<<GFG, HF>>>(W1, B1);

    // GEMM1: X = affine(Y) @ W1_top + HGW[batch], fused stats
    k_gemm_tc<0, 1, true><<<dim3(HF / 64, gm), TB>>>(pY, W1, pX, nullptr, batch, N, HF, HF);
    k_coef<<<1, HF>>>(go1, bo1, inv_n, HF);

    // GEMM2: Y = act(affine(X)) @ W2 + B2 (Nc=128), fused stats
    k_gemm_tc<1, 2, true><<<dim3(128 / 64, gm), TB>>>(pX, W2, pY, B2, nullptr, N, HF, 128);
    k_coef<<<1, HF>>>(go2, bo2, inv_n, 128);

    // GEMM3: out = act(affine(Y)) @ W3 + B3, split (mu, logvar)
    k_gemm_tc<2, 2, false><<<dim3(128 / 64, gm), TB>>>(pY, W3, (float*)d_out, B3, nullptr, N, 128, 128);

    (void)n_in; (void)out_size;
}

// round 6
// speedup vs baseline: 1.5358x; 1.0761x over previous
#include <cuda_runtime.h>
#include <cstdint>

// Problem constants: N=50000, E=300000, G=256, H=256, LAT=64
#define HF 256
#define GFG 256
#define LATF 64
#define NMAX 50000
#define EMAX 300000
#define BN_EPS 1e-5f

// ---- static scratch ----
__device__ __align__(128) float g_X[NMAX * HF];
__device__ __align__(128) float g_Y[NMAX * HF];
__device__ __align__(128) float g_HG[GFG * HF];
__device__ __align__(128) float g_HGW[GFG * HF];
__device__ __align__(16) float g_S[HF];     // invariant: zero at entry (k_coef re-zeroes)
__device__ __align__(16) float g_SS[HF];
__device__ __align__(16) float g_scale[HF];
__device__ __align__(16) float g_shift[HF];
// CSR scratch
__device__ int g_deg[NMAX];                 // invariant: zero at entry (k_scan re-zeroes)
__device__ int g_rowptr[NMAX + 1];
__device__ int g_cursor[NMAX];
__device__ __align__(16) int2 g_epack[EMAX];

// ---------------- helpers ----------------
__device__ __forceinline__ float sp(float x) {
    float t = __expf(-fabsf(x));
    return fmaxf(x, 0.f) + __logf(1.f + t);
}

__device__ __forceinline__ float4 sp4(float4 a, float4 b) {
    float4 r;
    r.x = sp(a.x + b.x);
    r.y = sp(a.y + b.y);
    r.z = sp(a.z + b.z);
    r.w = sp(a.w + b.w);
    return r;
}

__device__ __forceinline__ int lb(const int* __restrict__ a, int n, int key) {
    int lo = 0, hi = n;
    while (lo < hi) { int mid = (lo + hi) >> 1; if (a[mid] < key) lo = mid + 1; else hi = mid; }
    return lo;
}

__device__ __forceinline__ uint32_t f2tf32(float x) {
    uint32_t r;
    asm("cvt.rna.tf32.f32 %0, %1;" : "=r"(r) : "f"(x));
    return r;
}

__device__ __forceinline__ void mma_tf32(float c[4], uint32_t a0, uint32_t a1,
                                         uint32_t a2, uint32_t a3,
                                         uint32_t b0, uint32_t b1) {
    asm volatile(
        "mma.sync.aligned.m16n8k8.row.col.f32.tf32.tf32.f32 "
        "{%0,%1,%2,%3}, {%4,%5,%6,%7}, {%8,%9}, {%0,%1,%2,%3};"
        : "+f"(c[0]), "+f"(c[1]), "+f"(c[2]), "+f"(c[3])
        : "r"(a0), "r"(a1), "r"(a2), "r"(a3), "r"(b0), "r"(b1));
}

// ---------------- CSR build ----------------
// launch 1: histogram (g_deg is zero on entry by invariant)
__global__ void k_hist(const int* __restrict__ dst, int e_cnt) {
    int e = blockIdx.x * blockDim.x + threadIdx.x;
    if (e < e_cnt) atomicAdd(&g_deg[dst[e]], 1);
}

// launch 2: exclusive scan; re-zeroes g_deg for the next run
__global__ void k_scan(int n) {
    __shared__ int sm[1024];
    int t = threadIdx.x;
    int chunk = (n + 1023) >> 10;
    int lo = t * chunk, hi = min(lo + chunk, n);
    int sum = 0;
    for (int i = lo; i < hi; i++) sum += g_deg[i];
    sm[t] = sum;
    __syncthreads();
    for (int off = 1; off < 1024; off <<= 1) {
        int v = (t >= off) ? sm[t - off] : 0;
        __syncthreads();
        sm[t] += v;
        __syncthreads();
    }
    int run = sm[t] - sum;
    for (int i = lo; i < hi; i++) {
        int d = g_deg[i];
        g_rowptr[i] = run;
        g_cursor[i] = run;
        g_deg[i] = 0;          // restore invariant
        run += d;
    }
    if (t == 1023) g_rowptr[n] = run;
}

// launch 3: scatter edges by dst + node embedding (disjoint block ranges)
__global__ void k_scatter_embed(const int* __restrict__ src, const int* __restrict__ dst,
                                const int* __restrict__ et, int e_cnt, int e_blocks,
                                const int* __restrict__ nt, const float* __restrict__ emb,
                                int n) {
    if ((int)blockIdx.x < e_blocks) {
        int e = blockIdx.x * blockDim.x + threadIdx.x;
        if (e < e_cnt) {
            int pos = atomicAdd(&g_cursor[dst[e]], 1);
            g_epack[pos] = make_int2(src[e], et[e]);
        }
    } else {
        int i = (blockIdx.x - e_blocks) * blockDim.x + threadIdx.x;
        int total = n * (HF / 4);
        if (i < total) {
            int node = i / (HF / 4);
            int f4   = i % (HF / 4);
            ((float4*)g_X)[i] = __ldg((const float4*)emb + (size_t)nt[node] * (HF / 4) + f4);
        }
    }
}

// ---------------- core kernels ----------------

// launch 4 (PROFILED): Y[v] = X[v] + sum softplus(X[src]+ew[et]); 2-edge pipeline, no barriers
__global__ void __launch_bounds__(256) k_conv_csr(const float* __restrict__ ew, int n) {
    int grp = threadIdx.x >> 5;
    int lane = threadIdx.x & 31;
    int node = blockIdx.x * 8 + grp;
    if (node >= n) return;
    int lo = g_rowptr[node], hi = g_rowptr[node + 1];
    const float4* X4 = (const float4*)g_X;
    const float4* W4 = (const float4*)ew;
    int c = lane << 1;
    size_t nb = (size_t)node * 64 + c;
    float4 a0 = X4[nb];
    float4 a1 = X4[nb + 1];
    if (lo < hi) {
        int2 se = __ldg(&g_epack[lo]);
        const float4* xs = X4 + (size_t)se.x * 64 + c;
        const float4* ws = W4 + (size_t)se.y * 64 + c;
        float4 x0 = xs[0], x1 = xs[1];
        float4 w0 = __ldg(ws), w1 = __ldg(ws + 1);
        for (int k = lo + 1; k < hi; k++) {
            int2 se2 = __ldg(&g_epack[k]);
            const float4* xs2 = X4 + (size_t)se2.x * 64 + c;
            const float4* ws2 = W4 + (size_t)se2.y * 64 + c;
            float4 nx0 = xs2[0], nx1 = xs2[1];
            float4 nw0 = __ldg(ws2), nw1 = __ldg(ws2 + 1);
            float4 m0 = sp4(x0, w0);
            float4 m1 = sp4(x1, w1);
            a0.x += m0.x; a0.y += m0.y; a0.z += m0.z; a0.w += m0.w;
            a1.x += m1.x; a1.y += m1.y; a1.z += m1.z; a1.w += m1.w;
            x0 = nx0; x1 = nx1; w0 = nw0; w1 = nw1;
        }
        float4 m0 = sp4(x0, w0);
        float4 m1 = sp4(x1, w1);
        a0.x += m0.x; a0.y += m0.y; a0.z += m0.z; a0.w += m0.w;
        a1.x += m1.x; a1.y += m1.y; a1.z += m1.z; a1.w += m1.w;
    }
    float4* Y4 = (float4*)g_Y;
    Y4[nb] = a0;
    Y4[nb + 1] = a1;
}

// per-feature sum/sumsq of g_Y; MLP-8 front-batched (accumulates into zeroed g_S/g_SS)
__global__ void __launch_bounds__(256) k_stats(int n, int h) {
    int h4  = h >> 2;
    int gpb = 256 / h4;
    int col = threadIdx.x & (h4 - 1);
    int rof = threadIdx.x / h4;
    int stride = gridDim.x * gpb;
    float4 s  = make_float4(0.f, 0.f, 0.f, 0.f);
    float4 ss = make_float4(0.f, 0.f, 0.f, 0.f);
    const float4* Y4 = (const float4*)g_Y;
    for (int base = blockIdx.x * gpb + rof; base < n; base += stride * 8) {
        float4 v[8];
#pragma unroll
        for (int j = 0; j < 8; j++) {
            int r = base + j * stride;
            v[j] = (r < n) ? Y4[(size_t)r * h4 + col] : make_float4(0.f, 0.f, 0.f, 0.f);
        }
#pragma unroll
        for (int j = 0; j < 8; j++) {
            s.x += v[j].x; s.y += v[j].y; s.z += v[j].z; s.w += v[j].w;
            ss.x = fmaf(v[j].x, v[j].x, ss.x);
            ss.y = fmaf(v[j].y, v[j].y, ss.y);
            ss.z = fmaf(v[j].z, v[j].z, ss.z);
            ss.w = fmaf(v[j].w, v[j].w, ss.w);
        }
    }
    __shared__ float4 sh_s[256], sh_q[256];
    sh_s[threadIdx.x] = s;
    sh_q[threadIdx.x] = ss;
    __syncthreads();
    if (rof == 0) {
        for (int j = 1; j < gpb; j++) {
            float4 o = sh_s[j * h4 + col], q = sh_q[j * h4 + col];
            s.x += o.x; s.y += o.y; s.z += o.z; s.w += o.w;
            ss.x += q.x; ss.y += q.y; ss.z += q.z; ss.w += q.w;
        }
        int f = col << 2;
        atomicAdd(&g_S[f + 0], s.x);  atomicAdd(&g_S[f + 1], s.y);
        atomicAdd(&g_S[f + 2], s.z);  atomicAdd(&g_S[f + 3], s.w);
        atomicAdd(&g_SS[f + 0], ss.x); atomicAdd(&g_SS[f + 1], ss.y);
        atomicAdd(&g_SS[f + 2], ss.z); atomicAdd(&g_SS[f + 3], ss.w);
    }
}

// (scale,shift) from (S,SS,gamma,beta); re-zeroes S/SS (maintains invariant)
__global__ void k_coef(const float* __restrict__ gam, const float* __restrict__ bet,
                       float inv_n, int h) {
    int f = threadIdx.x;
    if (f < h) {
        float s = g_S[f], q = g_SS[f];
        float mu  = s * inv_n;
        float var = q * inv_n - mu * mu;
        float sc = __ldg(gam + f) * rsqrtf(var + BN_EPS);
        g_scale[f] = sc;
        g_shift[f] = __ldg(bet + f) - mu * sc;
        g_S[f] = 0.f;
        g_SS[f] = 0.f;
    }
}

// X = act(scale*Y + shift)
template <bool ACT>
__global__ void k_apply_coef(int n, int h) {
    int i = blockIdx.x * blockDim.x + threadIdx.x;
    int total = n * (h / 4);
    if (i >= total) return;
    int f4 = i % (h / 4);
    float4 y  = ((const float4*)g_Y)[i];
    float4 sc = ((const float4*)g_scale)[f4];
    float4 sh = ((const float4*)g_shift)[f4];
    float4 o;
    o.x = fmaf(y.x, sc.x, sh.x);
    o.y = fmaf(y.y, sc.y, sh.y);
    o.z = fmaf(y.z, sc.z, sh.z);
    o.w = fmaf(y.w, sc.w, sh.w);
    if (ACT) { o.x = sp(o.x); o.y = sp(o.y); o.z = sp(o.z); o.w = sp(o.w); }
    ((float4*)g_X)[i] = o;
}

// HG[g][f] = scale[f]*sum(Y rows of graph g) + cnt*shift[f]
__global__ void k_pool(const int* __restrict__ batch, int n) {
    int g = blockIdx.x;
    int f = threadIdx.x;
    __shared__ int slo, shi;
    if (f == 0) { slo = lb(batch, n, g); shi = lb(batch, n, g + 1); }
    __syncthreads();
    float s = 0.f;
    for (int r = slo; r < shi; r++) s += g_Y[(size_t)r * HF + f];
    g_HG[g * HF + f] = g_scale[f] * s + (float)(shi - slo) * g_shift[f];
}

__global__ void k_hgw(const float* __restrict__ W1, const float* __restrict__ B1) {
    int g = blockIdx.x;
    int f = threadIdx.x;
    __shared__ float hg[HF];
    hg[f] = g_HG[g * HF + f];
    __syncthreads();
    float acc = __ldg(B1 + f);
#pragma unroll 8
    for (int k = 0; k < HF; k++)
        acc = fmaf(hg[k], __ldg(W1 + (size_t)(HF + k) * HF + f), acc);
    g_HGW[g * HF + f] = acc;
}

// ======== TF32 TC GEMM with fused BN-affine on A and fused output stats ========
#define APITCH 36
#define BPITCH 68
template <int MODE, int AFF, bool STATS>
__global__ void __launch_bounds__(256)
k_gemm_tc(const float* __restrict__ A, const float* __restrict__ W,
          float* __restrict__ C, const float* __restrict__ bias,
          const int* __restrict__ batch, int M, int K, int Nc) {
    __shared__ uint32_t As[128 * APITCH];
    __shared__ uint32_t Bs[32 * BPITCH];
    __shared__ float smS[64], smQ[64];

    int tid = threadIdx.x;
    int lane = tid & 31, warp = tid >> 5;
    int wm = warp & 3, wn = warp >> 2;
    int g = lane >> 2, t = lane & 3;
    int m0 = blockIdx.y * 128, n0 = blockIdx.x * 64;

    if (STATS && tid < 64) { smS[tid] = 0.f; smQ[tid] = 0.f; }

    float acc[2][4][4];
#pragma unroll
    for (int i = 0; i < 2; i++)
#pragma unroll
        for (int j = 0; j < 4; j++)
#pragma unroll
            for (int k = 0; k < 4; k++) acc[i][j][k] = 0.f;

    int a_row[4], a_c4[4];
#pragma unroll
    for (int j = 0; j < 4; j++) {
        int idx = tid + j * 256;
        a_row[j] = idx >> 3;
        a_c4[j]  = idx & 7;
    }
    int b_row[2], b_c4[2];
#pragma unroll
    for (int j = 0; j < 2; j++) {
        int idx = tid + j * 256;
        b_row[j] = idx >> 4;
        b_c4[j]  = idx & 15;
    }

    auto loadA = [&](int r, int kc) -> float4 {
        float4 v = *(const float4*)(A + (size_t)r * K + kc);
        if (AFF >= 1) {
            float4 sc = *(const float4*)(g_scale + kc);
            float4 sh = *(const float4*)(g_shift + kc);
            v.x = fmaf(v.x, sc.x, sh.x);
            v.y = fmaf(v.y, sc.y, sh.y);
            v.z = fmaf(v.z, sc.z, sh.z);
            v.w = fmaf(v.w, sc.w, sh.w);
            if (AFF == 2) { v.x = sp(v.x); v.y = sp(v.y); v.z = sp(v.z); v.w = sp(v.w); }
        }
        return v;
    };

    float4 pa[4], pb[2];
#pragma unroll
    for (int j = 0; j < 4; j++) {
        int r = m0 + a_row[j]; if (r >= M) r = M - 1;
        pa[j] = loadA(r, a_c4[j] << 2);
    }
#pragma unroll
    for (int j = 0; j < 2; j++)
        pb[j] = __ldg((const float4*)(W + (size_t)b_row[j] * Nc + n0 + (b_c4[j] << 2)));

    int ktiles = K >> 5;
    for (int kt = 0; kt < ktiles; kt++) {
        __syncthreads();
#pragma unroll
        for (int j = 0; j < 4; j++) {
            uint4 u = make_uint4(f2tf32(pa[j].x), f2tf32(pa[j].y),
                                 f2tf32(pa[j].z), f2tf32(pa[j].w));
            *(uint4*)&As[a_row[j] * APITCH + (a_c4[j] << 2)] = u;
        }
#pragma unroll
        for (int j = 0; j < 2; j++) {
            uint4 u = make_uint4(f2tf32(pb[j].x), f2tf32(pb[j].y),
                                 f2tf32(pb[j].z), f2tf32(pb[j].w));
            *(uint4*)&Bs[b_row[j] * BPITCH + (b_c4[j] << 2)] = u;
        }
        __syncthreads();

        if (kt + 1 < ktiles) {
            int ko = (kt + 1) << 5;
#pragma unroll
            for (int j = 0; j < 4; j++) {
                int r = m0 + a_row[j]; if (r >= M) r = M - 1;
                pa[j] = loadA(r, ko + (a_c4[j] << 2));
            }
#pragma unroll
            for (int j = 0; j < 2; j++)
                pb[j] = __ldg((const float4*)(W + (size_t)(ko + b_row[j]) * Nc + n0 + (b_c4[j] << 2)));
        }

#pragma unroll
        for (int kk = 0; kk < 4; kk++) {
            int k8 = kk << 3;
            uint32_t af[2][4];
#pragma unroll
            for (int mt = 0; mt < 2; mt++) {
                int r = (wm << 5) + (mt << 4) + g;
                af[mt][0] = As[r * APITCH + k8 + t];
                af[mt][1] = As[(r + 8) * APITCH + k8 + t];
                af[mt][2] = As[r * APITCH + k8 + t + 4];
                af[mt][3] = As[(r + 8) * APITCH + k8 + t + 4];
            }
            uint32_t bf[4][2];
#pragma unroll
            for (int nt = 0; nt < 4; nt++) {
                int c = (wn << 5) + (nt << 3) + g;
                bf[nt][0] = Bs[(k8 + t) * BPITCH + c];
                bf[nt][1] = Bs[(k8 + t + 4) * BPITCH + c];
            }
#pragma unroll
            for (int mt = 0; mt < 2; mt++)
#pragma unroll
                for (int nt = 0; nt < 4; nt++)
                    mma_tf32(acc[mt][nt], af[mt][0], af[mt][1], af[mt][2], af[mt][3],
                             bf[nt][0], bf[nt][1]);
        }
    }

    float csum[8], csq[8];
#pragma unroll
    for (int j = 0; j < 8; j++) { csum[j] = 0.f; csq[j] = 0.f; }

    int row_w = m0 + (wm << 5), col_w = n0 + (wn << 5);
#pragma unroll
    for (int mt = 0; mt < 2; mt++) {
#pragma unroll
        for (int half = 0; half < 2; half++) {
            int row = row_w + (mt << 4) + g + (half << 3);
            if (row >= M) continue;
            int bg = 0;
            if (MODE == 0) bg = __ldg(batch + row);
#pragma unroll
            for (int nt = 0; nt < 4; nt++) {
                int col = col_w + (nt << 3) + (t << 1);
                float v0 = acc[mt][nt][half * 2 + 0];
                float v1 = acc[mt][nt][half * 2 + 1];
                if (MODE == 0) {
                    float2 hw = *(const float2*)(g_HGW + (size_t)bg * HF + col);
                    v0 += hw.x; v1 += hw.y;
                    *(float2*)(C + (size_t)row * Nc + col) = make_float2(v0, v1);
                } else {
                    float2 b2 = *(const float2*)(bias + col);
                    v0 += b2.x; v1 += b2.y;
                    if (MODE == 1) {
                        *(float2*)(C + (size_t)row * Nc + col) = make_float2(v0, v1);
                    } else {
                        if (col < LATF)
                            *(float2*)(C + (size_t)row * LATF + col) = make_float2(v0, v1);
                        else
                            *(float2*)(C + (size_t)M * LATF + (size_t)row * LATF + (col - LATF))
                                = make_float2(v0, v1);
                    }
                }
                if (STATS) {
                    int j = nt * 2;
                    csum[j]     += v0; csq[j]     = fmaf(v0, v0, csq[j]);
                    csum[j + 1] += v1; csq[j + 1] = fmaf(v1, v1, csq[j + 1]);
                }
            }
        }
    }

    if (STATS) {
#pragma unroll
        for (int j = 0; j < 8; j++) {
            csum[j] += __shfl_xor_sync(0xffffffffu, csum[j], 4);
            csum[j] += __shfl_xor_sync(0xffffffffu, csum[j], 8);
            csum[j] += __shfl_xor_sync(0xffffffffu, csum[j], 16);
            csq[j]  += __shfl_xor_sync(0xffffffffu, csq[j], 4);
            csq[j]  += __shfl_xor_sync(0xffffffffu, csq[j], 8);
            csq[j]  += __shfl_xor_sync(0xffffffffu, csq[j], 16);
        }
        if (g == 0) {
#pragma unroll
            for (int j = 0; j < 8; j++) {
                int lc = (wn << 5) + ((j >> 1) << 3) + (t << 1) + (j & 1);
                atomicAdd(&smS[lc], csum[j]);
                atomicAdd(&smQ[lc], csq[j]);
            }
        }
        __syncthreads();
        if (tid < 64) {
            atomicAdd(&g_S[n0 + tid], smS[tid]);
            atomicAdd(&g_SS[n0 + tid], smQ[tid]);
        }
    }
}

// ---------------- launch ----------------
extern "C" void kernel_launch(void* const* d_in, const int* in_sizes, int n_in,
                              void* d_out, int out_size) {
    const int*   node_type = (const int*)d_in[0];
    const int*   edge_type = (const int*)d_in[1];
    const int*   edge_index = (const int*)d_in[2];
    const int*   batch     = (const int*)d_in[3];
    const float* node_emb  = (const float*)d_in[4];
    const float* edge_emb  = (const float*)d_in[5];
    const float* g1 = (const float*)d_in[6],  *b1 = (const float*)d_in[7];
    const float* g2 = (const float*)d_in[8],  *b2 = (const float*)d_in[9];
    const float* g3 = (const float*)d_in[10], *b3 = (const float*)d_in[11];
    const float* go1 = (const float*)d_in[12], *bo1 = (const float*)d_in[13];
    const float* go2 = (const float*)d_in[14], *bo2 = (const float*)d_in[15];
    const float* W1 = (const float*)d_in[16], *B1 = (const float*)d_in[17];
    const float* W2 = (const float*)d_in[18], *B2 = (const float*)d_in[19];
    const float* W3 = (const float*)d_in[20], *B3 = (const float*)d_in[21];

    int N = in_sizes[0];
    int E = in_sizes[1];
    const int* src = edge_index;
    const int* dst = edge_index + E;

    float *pX, *pY;
    cudaGetSymbolAddress((void**)&pX, g_X);
    cudaGetSymbolAddress((void**)&pY, g_Y);

    const int TB = 256;
    float inv_n = 1.f / (float)N;
    int emb_gr = (N * (HF / 4) + TB - 1) / TB;
    int ap_gr256 = emb_gr;
    int gm = (N + 127) / 128;
    int cv_gr = (N + 7) / 8;
    int e_gr = (E + TB - 1) / TB;

    // ---- CSR build + embed (3 launches; g_deg zero by invariant) ----
    k_hist<<<e_gr, TB>>>(dst, E);                                   // 1
    k_scan<<<1, 1024>>>(N);                                         // 2
    k_scatter_embed<<<e_gr + emb_gr, TB>>>(src, dst, edge_type, E,  // 3
                                           e_gr, node_type, node_emb, N);

    // --- layer 1 ---
    k_conv_csr<<<cv_gr, TB>>>(edge_emb, N);                         // 4  <- profiled
    k_stats<<<1024, 256>>>(N, HF);                                  // 5
    k_coef<<<1, HF>>>(g1, b1, inv_n, HF);                           // 6
    k_apply_coef<true><<<ap_gr256, TB>>>(N, HF);                    // 7

    // --- layer 2 ---
    k_conv_csr<<<cv_gr, TB>>>(edge_emb, N);
    k_stats<<<1024, 256>>>(N, HF);
    k_coef<<<1, HF>>>(g2, b2, inv_n, HF);
    k_apply_coef<true><<<ap_gr256, TB>>>(N, HF);

    // --- layer 3 (no act; BN fused into pool & GEMM1 A-load) ---
    k_conv_csr<<<cv_gr, TB>>>(edge_emb, N);
    k_stats<<<1024, 256>>>(N, HF);
    k_coef<<<1, HF>>>(g3, b3, inv_n, HF);

    // pooling (affine inline) + HGW
    k_pool<<<GFG, HF>>>(batch, N);
    k_hgw<<<GFG, HF>>>(W1, B1);

    // GEMM1: X = affine(Y) @ W1_top + HGW[batch], fused stats
    k_gemm_tc<0, 1, true><<<dim3(HF / 64, gm), TB>>>(pY, W1, pX, nullptr, batch, N, HF, HF);
    k_coef<<<1, HF>>>(go1, bo1, inv_n, HF);

    // GEMM2: Y = act(affine(X)) @ W2 + B2 (Nc=128), fused stats
    k_gemm_tc<1, 2, true><<<dim3(128 / 64, gm), TB>>>(pX, W2, pY, B2, nullptr, N, HF, 128);
    k_coef<<<1, HF>>>(go2, bo2, inv_n, 128);

    // GEMM3: out = act(affine(Y)) @ W3 + B3, split (mu, logvar)
    k_gemm_tc<2, 2, false><<<dim3(128 / 64, gm), TB>>>(pY, W3, (float*)d_out, B3, nullptr, N, 128, 128);

    (void)n_in; (void)out_size;
}

// round 7
// speedup vs baseline: 1.5750x; 1.0256x over previous
#include <cuda_runtime.h>
#include <cstdint>

// Problem constants: N=50000, E=300000, G=256, H=256, LAT=64
#define HF 256
#define GFG 256
#define LATF 64
#define NMAX 50000
#define EMAX 300000
#define BN_EPS 1e-5f

// ---- static scratch ----
__device__ __align__(128) float g_X[NMAX * HF];
__device__ __align__(128) float g_Y[NMAX * HF];
__device__ __align__(128) float g_HGW[GFG * HF];
__device__ __align__(16) float g_S[HF];     // invariant: zero at entry (k_coef re-zeroes)
__device__ __align__(16) float g_SS[HF];
__device__ __align__(16) float g_scale[HF];
__device__ __align__(16) float g_shift[HF];
// CSR scratch
__device__ int g_deg[NMAX];                 // invariant: zero at entry (k_scan re-zeroes)
__device__ int g_rowptr[NMAX + 1];
__device__ int g_cursor[NMAX];
__device__ __align__(16) int2 g_epack[EMAX];

// ---------------- helpers ----------------
typedef unsigned long long u64;

__device__ __forceinline__ u64 pk2(float lo, float hi) {
    u64 r;
    asm("mov.b64 %0,{%1,%2};" : "=l"(r) : "f"(lo), "f"(hi));
    return r;
}
__device__ __forceinline__ void upk2(u64 v, float& lo, float& hi) {
    asm("mov.b64 {%0,%1},%2;" : "=f"(lo), "=f"(hi) : "l"(v));
}
__device__ __forceinline__ u64 addx2(u64 a, u64 b) {
    u64 r;
    asm("add.rn.f32x2 %0,%1,%2;" : "=l"(r) : "l"(a), "l"(b));
    return r;
}
__device__ __forceinline__ u64 mulx2(u64 a, u64 b) {
    u64 r;
    asm("mul.rn.f32x2 %0,%1,%2;" : "=l"(r) : "l"(a), "l"(b));
    return r;
}
__device__ __forceinline__ u64 fmax2(u64 a, u64 b, u64 c) {
    u64 r;
    asm("fma.rn.f32x2 %0,%1,%2,%3;" : "=l"(r) : "l"(a), "l"(b), "l"(c));
    return r;
}
__device__ __forceinline__ float ex2f(float x) {
    float r;
    asm("ex2.approx.ftz.f32 %0,%1;" : "=f"(r) : "f"(x));
    return r;
}
__device__ __forceinline__ float lg2f(float x) {
    float r;
    asm("lg2.approx.ftz.f32 %0,%1;" : "=f"(r) : "f"(x));
    return r;
}

#define ABS2  0x7FFFFFFF7FFFFFFFULL
#define NL2E2 0xBFB8AA3BBFB8AA3BULL   // -log2(e) x2
#define ONE2  0x3F8000003F800000ULL   // 1.0f x2
#define LN2X2 0x3F3172183F317218ULL   // ln(2) x2

// acc += softplus(x + w), 2 elements packed
__device__ __forceinline__ void sp2_acc(u64& acc, u64 x, u64 w) {
    u64 v  = addx2(x, w);
    u64 av = v & ABS2;
    u64 nz = mulx2(av, NL2E2);
    float n0, n1; upk2(nz, n0, n1);
    u64 t = addx2(pk2(ex2f(n0), ex2f(n1)), ONE2);
    float t0, t1; upk2(t, t0, t1);
    u64 l = pk2(lg2f(t0), lg2f(t1));
    float v0, v1; upk2(v, v0, v1);
    u64 m = pk2(fmaxf(v0, 0.f), fmaxf(v1, 0.f));
    acc = fmax2(l, LN2X2, acc);
    acc = addx2(acc, m);
}

__device__ __forceinline__ float sp(float x) {
    float t = ex2f(-fabsf(x) * 1.4426950408889634f);
    return fmaxf(x, 0.f) + lg2f(1.f + t) * 0.6931471805599453f;
}

__device__ __forceinline__ int lb(const int* __restrict__ a, int n, int key) {
    int lo = 0, hi = n;
    while (lo < hi) { int mid = (lo + hi) >> 1; if (a[mid] < key) lo = mid + 1; else hi = mid; }
    return lo;
}

__device__ __forceinline__ uint32_t f2tf32(float x) {
    uint32_t r;
    asm("cvt.rna.tf32.f32 %0, %1;" : "=r"(r) : "f"(x));
    return r;
}

__device__ __forceinline__ void mma_tf32(float c[4], uint32_t a0, uint32_t a1,
                                         uint32_t a2, uint32_t a3,
                                         uint32_t b0, uint32_t b1) {
    asm volatile(
        "mma.sync.aligned.m16n8k8.row.col.f32.tf32.tf32.f32 "
        "{%0,%1,%2,%3}, {%4,%5,%6,%7}, {%8,%9}, {%0,%1,%2,%3};"
        : "+f"(c[0]), "+f"(c[1]), "+f"(c[2]), "+f"(c[3])
        : "r"(a0), "r"(a1), "r"(a2), "r"(a3), "r"(b0), "r"(b1));
}

// ---------------- CSR build ----------------
__global__ void k_hist(const int* __restrict__ dst, int e_cnt) {
    int e = blockIdx.x * blockDim.x + threadIdx.x;
    if (e < e_cnt) atomicAdd(&g_deg[dst[e]], 1);
}

__global__ void k_scan(int n) {
    __shared__ int sm[1024];
    int t = threadIdx.x;
    int chunk = (n + 1023) >> 10;
    int lo = t * chunk, hi = min(lo + chunk, n);
    int sum = 0;
    for (int i = lo; i < hi; i++) sum += g_deg[i];
    sm[t] = sum;
    __syncthreads();
    for (int off = 1; off < 1024; off <<= 1) {
        int v = (t >= off) ? sm[t - off] : 0;
        __syncthreads();
        sm[t] += v;
        __syncthreads();
    }
    int run = sm[t] - sum;
    for (int i = lo; i < hi; i++) {
        int d = g_deg[i];
        g_rowptr[i] = run;
        g_cursor[i] = run;
        g_deg[i] = 0;
        run += d;
    }
    if (t == 1023) g_rowptr[n] = run;
}

// scatter (premultiplied float4-row offsets) + embed, disjoint block ranges
__global__ void k_scatter_embed(const int* __restrict__ src, const int* __restrict__ dst,
                                const int* __restrict__ et, int e_cnt, int e_blocks,
                                const int* __restrict__ nt, const float* __restrict__ emb,
                                int n) {
    if ((int)blockIdx.x < e_blocks) {
        int e = blockIdx.x * blockDim.x + threadIdx.x;
        if (e < e_cnt) {
            int pos = atomicAdd(&g_cursor[dst[e]], 1);
            g_epack[pos] = make_int2(src[e] << 6, et[e] << 6);
        }
    } else {
        int i = (blockIdx.x - e_blocks) * blockDim.x + threadIdx.x;
        int total = n * (HF / 4);
        if (i < total) {
            int node = i / (HF / 4);
            int f4   = i % (HF / 4);
            ((float4*)g_X)[i] = __ldg((const float4*)emb + (size_t)nt[node] * (HF / 4) + f4);
        }
    }
}

// ---------------- core kernels ----------------

// Y[v] = X[v] + sum softplus(X[src]+ew[et]); f32x2 packed math, 2-edge pipeline
__global__ void __launch_bounds__(256) k_conv_csr(const float* __restrict__ ew, int n) {
    int grp = threadIdx.x >> 5;
    int lane = threadIdx.x & 31;
    int node = blockIdx.x * 8 + grp;
    if (node >= n) return;
    int lo = g_rowptr[node], hi = g_rowptr[node + 1];
    const float4* X4 = (const float4*)g_X;
    const float4* W4 = (const float4*)ew;
    int c = lane << 1;
    size_t nb = (size_t)node * 64 + c;
    float4 i0 = X4[nb];
    float4 i1 = X4[nb + 1];
    u64 a0 = pk2(i0.x, i0.y), a1 = pk2(i0.z, i0.w);
    u64 a2 = pk2(i1.x, i1.y), a3 = pk2(i1.z, i1.w);
    if (lo < hi) {
        int2 se = __ldg(&g_epack[lo]);
        const float4* xs = X4 + (size_t)(se.x + c);
        const float4* ws = W4 + (size_t)(se.y + c);
        float4 x0 = xs[0], x1 = xs[1];
        float4 w0 = __ldg(ws), w1 = __ldg(ws + 1);
        for (int k = lo + 1; k < hi; k++) {
            int2 se2 = __ldg(&g_epack[k]);
            const float4* xs2 = X4 + (size_t)(se2.x + c);
            const float4* ws2 = W4 + (size_t)(se2.y + c);
            float4 nx0 = xs2[0], nx1 = xs2[1];
            float4 nw0 = __ldg(ws2), nw1 = __ldg(ws2 + 1);
            sp2_acc(a0, pk2(x0.x, x0.y), pk2(w0.x, w0.y));
            sp2_acc(a1, pk2(x0.z, x0.w), pk2(w0.z, w0.w));
            sp2_acc(a2, pk2(x1.x, x1.y), pk2(w1.x, w1.y));
            sp2_acc(a3, pk2(x1.z, x1.w), pk2(w1.z, w1.w));
            x0 = nx0; x1 = nx1; w0 = nw0; w1 = nw1;
        }
        sp2_acc(a0, pk2(x0.x, x0.y), pk2(w0.x, w0.y));
        sp2_acc(a1, pk2(x0.z, x0.w), pk2(w0.z, w0.w));
        sp2_acc(a2, pk2(x1.x, x1.y), pk2(w1.x, w1.y));
        sp2_acc(a3, pk2(x1.z, x1.w), pk2(w1.z, w1.w));
    }
    float4 o0, o1;
    upk2(a0, o0.x, o0.y); upk2(a1, o0.z, o0.w);
    upk2(a2, o1.x, o1.y); upk2(a3, o1.z, o1.w);
    float4* Y4 = (float4*)g_Y;
    Y4[nb] = o0;
    Y4[nb + 1] = o1;
}

// per-feature sum/sumsq of g_Y; MLP-8 front-batched
__global__ void __launch_bounds__(256) k_stats(int n, int h) {
    int h4  = h >> 2;
    int gpb = 256 / h4;
    int col = threadIdx.x & (h4 - 1);
    int rof = threadIdx.x / h4;
    int stride = gridDim.x * gpb;
    float4 s  = make_float4(0.f, 0.f, 0.f, 0.f);
    float4 ss = make_float4(0.f, 0.f, 0.f, 0.f);
    const float4* Y4 = (const float4*)g_Y;
    for (int base = blockIdx.x * gpb + rof; base < n; base += stride * 8) {
        float4 v[8];
#pragma unroll
        for (int j = 0; j < 8; j++) {
            int r = base + j * stride;
            v[j] = (r < n) ? Y4[(size_t)r * h4 + col] : make_float4(0.f, 0.f, 0.f, 0.f);
        }
#pragma unroll
        for (int j = 0; j < 8; j++) {
            s.x += v[j].x; s.y += v[j].y; s.z += v[j].z; s.w += v[j].w;
            ss.x = fmaf(v[j].x, v[j].x, ss.x);
            ss.y = fmaf(v[j].y, v[j].y, ss.y);
            ss.z = fmaf(v[j].z, v[j].z, ss.z);
            ss.w = fmaf(v[j].w, v[j].w, ss.w);
        }
    }
    __shared__ float4 sh_s[256], sh_q[256];
    sh_s[threadIdx.x] = s;
    sh_q[threadIdx.x] = ss;
    __syncthreads();
    if (rof == 0) {
        for (int j = 1; j < gpb; j++) {
            float4 o = sh_s[j * h4 + col], q = sh_q[j * h4 + col];
            s.x += o.x; s.y += o.y; s.z += o.z; s.w += o.w;
            ss.x += q.x; ss.y += q.y; ss.z += q.z; ss.w += q.w;
        }
        int f = col << 2;
        atomicAdd(&g_S[f + 0], s.x);  atomicAdd(&g_S[f + 1], s.y);
        atomicAdd(&g_S[f + 2], s.z);  atomicAdd(&g_S[f + 3], s.w);
        atomicAdd(&g_SS[f + 0], ss.x); atomicAdd(&g_SS[f + 1], ss.y);
        atomicAdd(&g_SS[f + 2], ss.z); atomicAdd(&g_SS[f + 3], ss.w);
    }
}

__global__ void k_coef(const float* __restrict__ gam, const float* __restrict__ bet,
                       float inv_n, int h) {
    int f = threadIdx.x;
    if (f < h) {
        float s = g_S[f], q = g_SS[f];
        float mu  = s * inv_n;
        float var = q * inv_n - mu * mu;
        float sc = __ldg(gam + f) * rsqrtf(var + BN_EPS);
        g_scale[f] = sc;
        g_shift[f] = __ldg(bet + f) - mu * sc;
        g_S[f] = 0.f;
        g_SS[f] = 0.f;
    }
}

template <bool ACT>
__global__ void k_apply_coef(int n, int h) {
    int i = blockIdx.x * blockDim.x + threadIdx.x;
    int total = n * (h / 4);
    if (i >= total) return;
    int f4 = i % (h / 4);
    float4 y  = ((const float4*)g_Y)[i];
    float4 sc = ((const float4*)g_scale)[f4];
    float4 sh = ((const float4*)g_shift)[f4];
    float4 o;
    o.x = fmaf(y.x, sc.x, sh.x);
    o.y = fmaf(y.y, sc.y, sh.y);
    o.z = fmaf(y.z, sc.z, sh.z);
    o.w = fmaf(y.w, sc.w, sh.w);
    if (ACT) { o.x = sp(o.x); o.y = sp(o.y); o.z = sp(o.z); o.w = sp(o.w); }
    ((float4*)g_X)[i] = o;
}

// fused pool + HGW: block g pools affine(Y) rows into smem, then HGW = HG @ W1_bot + B1
__global__ void k_pool_hgw(const int* __restrict__ batch, int n,
                           const float* __restrict__ W1, const float* __restrict__ B1) {
    int g = blockIdx.x;
    int f = threadIdx.x;
    __shared__ int slo, shi;
    __shared__ float hg[HF];
    if (f == 0) { slo = lb(batch, n, g); shi = lb(batch, n, g + 1); }
    __syncthreads();
    float s = 0.f;
    for (int r = slo; r < shi; r++) s += g_Y[(size_t)r * HF + f];
    hg[f] = g_scale[f] * s + (float)(shi - slo) * g_shift[f];
    __syncthreads();
    float acc = __ldg(B1 + f);
#pragma unroll 8
    for (int k = 0; k < HF; k++)
        acc = fmaf(hg[k], __ldg(W1 + (size_t)(HF + k) * HF + f), acc);
    g_HGW[g * HF + f] = acc;
}

// ======== TF32 TC GEMM, double-buffered smem (1 sync/ktile), fused affine + stats ====
#define APITCH 36
#define BPITCH 68
#define ASZ (128 * APITCH)
#define BSZ (32 * BPITCH)
#define GEMM_SMEM ((2 * ASZ + 2 * BSZ) * 4)

template <int MODE, int AFF, bool STATS>
__global__ void __launch_bounds__(256)
k_gemm_tc(const float* __restrict__ A, const float* __restrict__ W,
          float* __restrict__ C, const float* __restrict__ bias,
          const int* __restrict__ batch, int M, int K, int Nc) {
    extern __shared__ uint32_t dynsm[];
    uint32_t* As = dynsm;            // 2 * ASZ
    uint32_t* Bs = dynsm + 2 * ASZ;  // 2 * BSZ
    __shared__ float smS[64], smQ[64];

    int tid = threadIdx.x;
    int lane = tid & 31, warp = tid >> 5;
    int wm = warp & 3, wn = warp >> 2;
    int g = lane >> 2, t = lane & 3;
    int m0 = blockIdx.y * 128, n0 = blockIdx.x * 64;

    if (STATS && tid < 64) { smS[tid] = 0.f; smQ[tid] = 0.f; }

    float acc[2][4][4];
#pragma unroll
    for (int i = 0; i < 2; i++)
#pragma unroll
        for (int j = 0; j < 4; j++)
#pragma unroll
            for (int k = 0; k < 4; k++) acc[i][j][k] = 0.f;

    int a_row[4], a_c4[4];
#pragma unroll
    for (int j = 0; j < 4; j++) {
        int idx = tid + j * 256;
        a_row[j] = idx >> 3;
        a_c4[j]  = idx & 7;
    }
    int b_row[2], b_c4[2];
#pragma unroll
    for (int j = 0; j < 2; j++) {
        int idx = tid + j * 256;
        b_row[j] = idx >> 4;
        b_c4[j]  = idx & 15;
    }

    auto loadA = [&](int r, int kc) -> float4 {
        float4 v = *(const float4*)(A + (size_t)r * K + kc);
        if (AFF >= 1) {
            float4 sc = *(const float4*)(g_scale + kc);
            float4 sh = *(const float4*)(g_shift + kc);
            v.x = fmaf(v.x, sc.x, sh.x);
            v.y = fmaf(v.y, sc.y, sh.y);
            v.z = fmaf(v.z, sc.z, sh.z);
            v.w = fmaf(v.w, sc.w, sh.w);
            if (AFF == 2) { v.x = sp(v.x); v.y = sp(v.y); v.z = sp(v.z); v.w = sp(v.w); }
        }
        return v;
    };

    float4 pa[4], pb[2];
#pragma unroll
    for (int j = 0; j < 4; j++) {
        int r = m0 + a_row[j]; if (r >= M) r = M - 1;
        pa[j] = loadA(r, a_c4[j] << 2);
    }
#pragma unroll
    for (int j = 0; j < 2; j++)
        pb[j] = __ldg((const float4*)(W + (size_t)b_row[j] * Nc + n0 + (b_c4[j] << 2)));

    // store tile 0 into buffer 0
#pragma unroll
    for (int j = 0; j < 4; j++) {
        uint4 u = make_uint4(f2tf32(pa[j].x), f2tf32(pa[j].y),
                             f2tf32(pa[j].z), f2tf32(pa[j].w));
        *(uint4*)&As[a_row[j] * APITCH + (a_c4[j] << 2)] = u;
    }
#pragma unroll
    for (int j = 0; j < 2; j++) {
        uint4 u = make_uint4(f2tf32(pb[j].x), f2tf32(pb[j].y),
                             f2tf32(pb[j].z), f2tf32(pb[j].w));
        *(uint4*)&Bs[b_row[j] * BPITCH + (b_c4[j] << 2)] = u;
    }
    __syncthreads();

    int ktiles = K >> 5;
    int buf = 0;
    for (int kt = 0; kt < ktiles; kt++) {
        bool hn = (kt + 1 < ktiles);
        if (hn) {
            int ko = (kt + 1) << 5;
#pragma unroll
            for (int j = 0; j < 4; j++) {
                int r = m0 + a_row[j]; if (r >= M) r = M - 1;
                pa[j] = loadA(r, ko + (a_c4[j] << 2));
            }
#pragma unroll
            for (int j = 0; j < 2; j++)
                pb[j] = __ldg((const float4*)(W + (size_t)(ko + b_row[j]) * Nc + n0 + (b_c4[j] << 2)));
        }

        const uint32_t* Ab = As + buf * ASZ;
        const uint32_t* Bb = Bs + buf * BSZ;
#pragma unroll
        for (int kk = 0; kk < 4; kk++) {
            int k8 = kk << 3;
            uint32_t af[2][4];
#pragma unroll
            for (int mt = 0; mt < 2; mt++) {
                int r = (wm << 5) + (mt << 4) + g;
                af[mt][0] = Ab[r * APITCH + k8 + t];
                af[mt][1] = Ab[(r + 8) * APITCH + k8 + t];
                af[mt][2] = Ab[r * APITCH + k8 + t + 4];
                af[mt][3] = Ab[(r + 8) * APITCH + k8 + t + 4];
            }
            uint32_t bf[4][2];
#pragma unroll
            for (int nt = 0; nt < 4; nt++) {
                int c = (wn << 5) + (nt << 3) + g;
                bf[nt][0] = Bb[(k8 + t) * BPITCH + c];
                bf[nt][1] = Bb[(k8 + t + 4) * BPITCH + c];
            }
#pragma unroll
            for (int mt = 0; mt < 2; mt++)
#pragma unroll
                for (int nt = 0; nt < 4; nt++)
                    mma_tf32(acc[mt][nt], af[mt][0], af[mt][1], af[mt][2], af[mt][3],
                             bf[nt][0], bf[nt][1]);
        }

        if (hn) {
            uint32_t* An = As + (buf ^ 1) * ASZ;
            uint32_t* Bn = Bs + (buf ^ 1) * BSZ;
#pragma unroll
            for (int j = 0; j < 4; j++) {
                uint4 u = make_uint4(f2tf32(pa[j].x), f2tf32(pa[j].y),
                                     f2tf32(pa[j].z), f2tf32(pa[j].w));
                *(uint4*)&An[a_row[j] * APITCH + (a_c4[j] << 2)] = u;
            }
#pragma unroll
            for (int j = 0; j < 2; j++) {
                uint4 u = make_uint4(f2tf32(pb[j].x), f2tf32(pb[j].y),
                                     f2tf32(pb[j].z), f2tf32(pb[j].w));
                *(uint4*)&Bn[b_row[j] * BPITCH + (b_c4[j] << 2)] = u;
            }
            __syncthreads();
            buf ^= 1;
        }
    }

    float csum[8], csq[8];
#pragma unroll
    for (int j = 0; j < 8; j++) { csum[j] = 0.f; csq[j] = 0.f; }

    int row_w = m0 + (wm << 5), col_w = n0 + (wn << 5);
#pragma unroll
    for (int mt = 0; mt < 2; mt++) {
#pragma unroll
        for (int half = 0; half < 2; half++) {
            int row = row_w + (mt << 4) + g + (half << 3);
            if (row >= M) continue;
            int bg = 0;
            if (MODE == 0) bg = __ldg(batch + row);
#pragma unroll
            for (int nt = 0; nt < 4; nt++) {
                int col = col_w + (nt << 3) + (t << 1);
                float v0 = acc[mt][nt][half * 2 + 0];
                float v1 = acc[mt][nt][half * 2 + 1];
                if (MODE == 0) {
                    float2 hw = *(const float2*)(g_HGW + (size_t)bg * HF + col);
                    v0 += hw.x; v1 += hw.y;
                    *(float2*)(C + (size_t)row * Nc + col) = make_float2(v0, v1);
                } else {
                    float2 b2 = *(const float2*)(bias + col);
                    v0 += b2.x; v1 += b2.y;
                    if (MODE == 1) {
                        *(float2*)(C + (size_t)row * Nc + col) = make_float2(v0, v1);
                    } else {
                        if (col < LATF)
                            *(float2*)(C + (size_t)row * LATF + col) = make_float2(v0, v1);
                        else
                            *(float2*)(C + (size_t)M * LATF + (size_t)row * LATF + (col - LATF))
                                = make_float2(v0, v1);
                    }
                }
                if (STATS) {
                    int j = nt * 2;
                    csum[j]     += v0; csq[j]     = fmaf(v0, v0, csq[j]);
                    csum[j + 1] += v1; csq[j + 1] = fmaf(v1, v1, csq[j + 1]);
                }
            }
        }
    }

    if (STATS) {
#pragma unroll
        for (int j = 0; j < 8; j++) {
            csum[j] += __shfl_xor_sync(0xffffffffu, csum[j], 4);
            csum[j] += __shfl_xor_sync(0xffffffffu, csum[j], 8);
            csum[j] += __shfl_xor_sync(0xffffffffu, csum[j], 16);
            csq[j]  += __shfl_xor_sync(0xffffffffu, csq[j], 4);
            csq[j]  += __shfl_xor_sync(0xffffffffu, csq[j], 8);
            csq[j]  += __shfl_xor_sync(0xffffffffu, csq[j], 16);
        }
        if (g == 0) {
#pragma unroll
            for (int j = 0; j < 8; j++) {
                int lc = (wn << 5) + ((j >> 1) << 3) + (t << 1) + (j & 1);
                atomicAdd(&smS[lc], csum[j]);
                atomicAdd(&smQ[lc], csq[j]);
            }
        }
        __syncthreads();
        if (tid < 64) {
            atomicAdd(&g_S[n0 + tid], smS[tid]);
            atomicAdd(&g_SS[n0 + tid], smQ[tid]);
        }
    }
}

// ---------------- launch ----------------
extern "C" void kernel_launch(void* const* d_in, const int* in_sizes, int n_in,
                              void* d_out, int out_size) {
    const int*   node_type = (const int*)d_in[0];
    const int*   edge_type = (const int*)d_in[1];
    const int*   edge_index = (const int*)d_in[2];
    const int*   batch     = (const int*)d_in[3];
    const float* node_emb  = (const float*)d_in[4];
    const float* edge_emb  = (const float*)d_in[5];
    const float* g1 = (const float*)d_in[6],  *b1 = (const float*)d_in[7];
    const float* g2 = (const float*)d_in[8],  *b2 = (const float*)d_in[9];
    const float* g3 = (const float*)d_in[10], *b3 = (const float*)d_in[11];
    const float* go1 = (const float*)d_in[12], *bo1 = (const float*)d_in[13];
    const float* go2 = (const float*)d_in[14], *bo2 = (const float*)d_in[15];
    const float* W1 = (const float*)d_in[16], *B1 = (const float*)d_in[17];
    const float* W2 = (const float*)d_in[18], *B2 = (const float*)d_in[19];
    const float* W3 = (const float*)d_in[20], *B3 = (const float*)d_in[21];

    int N = in_sizes[0];
    int E = in_sizes[1];
    const int* src = edge_index;
    const int* dst = edge_index + E;

    float *pX, *pY;
    cudaGetSymbolAddress((void**)&pX, g_X);
    cudaGetSymbolAddress((void**)&pY, g_Y);

    static bool attr_set = false;
    if (!attr_set) {
        cudaFuncSetAttribute(k_gemm_tc<0, 1, true>,
                             cudaFuncAttributeMaxDynamicSharedMemorySize, GEMM_SMEM);
        cudaFuncSetAttribute(k_gemm_tc<1, 2, true>,
                             cudaFuncAttributeMaxDynamicSharedMemorySize, GEMM_SMEM);
        cudaFuncSetAttribute(k_gemm_tc<2, 2, false>,
                             cudaFuncAttributeMaxDynamicSharedMemorySize, GEMM_SMEM);
        attr_set = true;
    }

    const int TB = 256;
    float inv_n = 1.f / (float)N;
    int emb_gr = (N * (HF / 4) + TB - 1) / TB;
    int ap_gr256 = emb_gr;
    int gm = (N + 127) / 128;
    int cv_gr = (N + 7) / 8;
    int e_gr = (E + TB - 1) / TB;

    // ---- CSR build + embed ----
    k_hist<<<e_gr, TB>>>(dst, E);                                   // 1
    k_scan<<<1, 1024>>>(N);                                         // 2
    k_scatter_embed<<<e_gr + emb_gr, TB>>>(src, dst, edge_type, E,  // 3
                                           e_gr, node_type, node_emb, N);

    // --- layer 1 ---
    k_conv_csr<<<cv_gr, TB>>>(edge_emb, N);                         // 4 <- profiled
    k_stats<<<1024, 256>>>(N, HF);
    k_coef<<<1, HF>>>(g1, b1, inv_n, HF);
    k_apply_coef<true><<<ap_gr256, TB>>>(N, HF);

    // --- layer 2 ---
    k_conv_csr<<<cv_gr, TB>>>(edge_emb, N);
    k_stats<<<1024, 256>>>(N, HF);
    k_coef<<<1, HF>>>(g2, b2, inv_n, HF);
    k_apply_coef<true><<<ap_gr256, TB>>>(N, HF);

    // --- layer 3 (no act; BN fused into pool & GEMM1 A-load) ---
    k_conv_csr<<<cv_gr, TB>>>(edge_emb, N);
    k_stats<<<1024, 256>>>(N, HF);
    k_coef<<<1, HF>>>(g3, b3, inv_n, HF);

    // fused pooling + HGW
    k_pool_hgw<<<GFG, HF>>>(batch, N, W1, B1);

    // GEMM1: X = affine(Y) @ W1_top + HGW[batch], fused stats
    k_gemm_tc<0, 1, true><<<dim3(HF / 64, gm), TB, GEMM_SMEM>>>(pY, W1, pX, nullptr, batch, N, HF, HF);
    k_coef<<<1, HF>>>(go1, bo1, inv_n, HF);

    // GEMM2: Y = act(affine(X)) @ W2 + B2 (Nc=128), fused stats
    k_gemm_tc<1, 2, true><<<dim3(128 / 64, gm), TB, GEMM_SMEM>>>(pX, W2, pY, B2, nullptr, N, HF, 128);
    k_coef<<<1, HF>>>(go2, bo2, inv_n, 128);

    // GEMM3: out = act(affine(Y)) @ W3 + B3, split (mu, logvar)
    k_gemm_tc<2, 2, false><<<dim3(128 / 64, gm), TB, GEMM_SMEM>>>(pY, W3, (float*)d_out, B3, nullptr, N, 128, 128);

    (void)n_in; (void)out_size;
}